// round 1
// baseline (speedup 1.0000x reference)
#include <cuda_runtime.h>

// ============================================================================
// EdgeTransformerLayer  (B=2, N=64, D=256, H=8, DK=32, DFF=1024)
//
// Pipeline (8 launches, all graph-capturable):
//   1. ln1:      h   = LN(x; g1,be1)                       [8192,256]
//   2. proj(z4): lk,rk,lv,rv = h @ W{lk,rk,lv,rv}          4x [8192,256]
//   3. attn:     triangle attention (online softmax over a) -> att [8192,256]
//   4. wo:       hres = att @ Wo + h                       [8192,256]
//   5. ln2:      h2  = LN(hres; g2,be2)                    [8192,256]
//   6. ffn1:     t   = relu(h2 @ W1 + b1)                  [8192,1024]
//   7. ffn2:     out = t @ W2 + b2 + h2                    [8192,256]
// ============================================================================

namespace {
constexpr int Bb  = 2;
constexpr int Nn  = 64;
constexpr int Dd  = 256;
constexpr int Hh  = 8;
constexpr int DKk = 32;
constexpr int DFF = 1024;
constexpr int RR  = Bb * Nn * Nn;   // 8192 rows
}

// ---- scratch (device globals; no allocation allowed) -----------------------
__device__ float g_h   [RR * Dd];
__device__ float g_lk  [RR * Dd];
__device__ float g_rk  [RR * Dd];
__device__ float g_lv  [RR * Dd];
__device__ float g_rv  [RR * Dd];
__device__ float g_att [RR * Dd];
__device__ float g_hres[RR * Dd];
__device__ float g_h2  [RR * Dd];
__device__ float g_ffn [RR * DFF];

// ============================================================================
// LayerNorm: one block per row, 256 threads, 1 element/thread
// ============================================================================
__device__ __forceinline__ void ln_body(const float* __restrict__ in,
                                        const float* __restrict__ gam,
                                        const float* __restrict__ bet,
                                        float* __restrict__ out)
{
    const int row = blockIdx.x;
    const int t   = threadIdx.x;
    const float v = in[row * Dd + t];
    float s = v, s2 = v * v;
#pragma unroll
    for (int o = 16; o; o >>= 1) {
        s  += __shfl_xor_sync(0xffffffffu, s,  o);
        s2 += __shfl_xor_sync(0xffffffffu, s2, o);
    }
    __shared__ float ws[8], ws2[8];
    if ((t & 31) == 0) { ws[t >> 5] = s; ws2[t >> 5] = s2; }
    __syncthreads();
    float ts = 0.f, ts2 = 0.f;
#pragma unroll
    for (int i = 0; i < 8; i++) { ts += ws[i]; ts2 += ws2[i]; }
    const float mean = ts * (1.0f / Dd);
    const float var  = ts2 * (1.0f / Dd) - mean * mean;
    const float inv  = rsqrtf(var + 1e-5f);
    out[row * Dd + t] = (v - mean) * inv * gam[t] + bet[t];
}

__global__ __launch_bounds__(256) void ln1_kernel(const float* __restrict__ x,
                                                  const float* __restrict__ g1,
                                                  const float* __restrict__ be1)
{
    ln_body(x, g1, be1, g_h);
}

__global__ __launch_bounds__(256) void ln2_kernel(const float* __restrict__ g2,
                                                  const float* __restrict__ be2)
{
    ln_body(g_hres, g2, be2, g_h2);
}

// ============================================================================
// fp32 tiled GEMM: C[M,Nc] = A[M,K] @ B[K,Nc]  (+ epilogues)
// Block tile 128x128, BK=16, 256 threads, 8x8 microtile per thread.
// EPI: 0 = none; 1 = +Cadd; 2 = +bias, relu; 3 = +bias, +Cadd
// M % 128 == 0, Nc % 128 == 0, K % 16 == 0 (true for all call sites).
// ============================================================================
template <int EPI>
__device__ __forceinline__ void gemm_body(const float* __restrict__ A,
                                          const float* __restrict__ Bm,
                                          const float* __restrict__ Cadd,
                                          const float* __restrict__ bias,
                                          float* __restrict__ C,
                                          int M, int Nc, int K)
{
    __shared__ float As[16][128];   // transposed A tile
    __shared__ float Bs[16][128];

    const int bm  = blockIdx.y * 128;
    const int bn  = blockIdx.x * 128;
    const int tid = threadIdx.x;
    const int tx  = tid & 15;       // 0..15 -> col group
    const int ty  = tid >> 4;       // 0..15 -> row group

    float acc[8][8];
#pragma unroll
    for (int i = 0; i < 8; i++)
#pragma unroll
        for (int j = 0; j < 8; j++) acc[i][j] = 0.f;

    // A tile load: 128 rows x 16 k; thread -> row = tid>>1, k-offset = (tid&1)*8
    const int a_row = tid >> 1;
    const int a_k   = (tid & 1) * 8;
    // B tile load: 16 rows x 128 cols; thread -> row = tid>>4, col = (tid&15)*8
    const int b_row = tid >> 4;
    const int b_col = (tid & 15) * 8;

    const float* Ap = A + (bm + a_row) * K + a_k;
    const float* Bp = Bm + b_row * Nc + bn + b_col;

    for (int k0 = 0; k0 < K; k0 += 16) {
        const float4 a0 = *(const float4*)(Ap);
        const float4 a1 = *(const float4*)(Ap + 4);
        const float4 b0 = *(const float4*)(Bp);
        const float4 b1 = *(const float4*)(Bp + 4);
        Ap += 16;
        Bp += 16 * Nc;

        As[a_k + 0][a_row] = a0.x; As[a_k + 1][a_row] = a0.y;
        As[a_k + 2][a_row] = a0.z; As[a_k + 3][a_row] = a0.w;
        As[a_k + 4][a_row] = a1.x; As[a_k + 5][a_row] = a1.y;
        As[a_k + 6][a_row] = a1.z; As[a_k + 7][a_row] = a1.w;
        *(float4*)&Bs[b_row][b_col]     = b0;
        *(float4*)&Bs[b_row][b_col + 4] = b1;
        __syncthreads();

#pragma unroll
        for (int kk = 0; kk < 16; kk++) {
            float ra[8], rb[8];
            *(float4*)&ra[0] = *(const float4*)&As[kk][ty * 8];
            *(float4*)&ra[4] = *(const float4*)&As[kk][ty * 8 + 4];
            *(float4*)&rb[0] = *(const float4*)&Bs[kk][tx * 8];
            *(float4*)&rb[4] = *(const float4*)&Bs[kk][tx * 8 + 4];
#pragma unroll
            for (int i = 0; i < 8; i++)
#pragma unroll
                for (int j = 0; j < 8; j++)
                    acc[i][j] += ra[i] * rb[j];
        }
        __syncthreads();
    }

    // epilogue: float4 stores
#pragma unroll
    for (int i = 0; i < 8; i++) {
        const int r = bm + ty * 8 + i;
#pragma unroll
        for (int j = 0; j < 8; j += 4) {
            const int c = bn + tx * 8 + j;
            float4 v;
            v.x = acc[i][j]; v.y = acc[i][j + 1]; v.z = acc[i][j + 2]; v.w = acc[i][j + 3];
            if (EPI == 2 || EPI == 3) {
                const float4 bb = *(const float4*)&bias[c];
                v.x += bb.x; v.y += bb.y; v.z += bb.z; v.w += bb.w;
            }
            if (EPI == 2) {
                v.x = fmaxf(v.x, 0.f); v.y = fmaxf(v.y, 0.f);
                v.z = fmaxf(v.z, 0.f); v.w = fmaxf(v.w, 0.f);
            }
            if (EPI == 1 || EPI == 3) {
                const float4 cc = *(const float4*)&Cadd[r * Nc + c];
                v.x += cc.x; v.y += cc.y; v.z += cc.z; v.w += cc.w;
            }
            *(float4*)&C[r * Nc + c] = v;
        }
    }
}

// ---- GEMM wrapper kernels (bind device-global scratch directly) ------------
__global__ __launch_bounds__(256) void k_proj(const float* __restrict__ Wlk,
                                              const float* __restrict__ Wrk,
                                              const float* __restrict__ Wlv,
                                              const float* __restrict__ Wrv)
{
    const float* Bp; float* Cp;
    switch (blockIdx.z) {
        case 0:  Bp = Wlk; Cp = g_lk; break;
        case 1:  Bp = Wrk; Cp = g_rk; break;
        case 2:  Bp = Wlv; Cp = g_lv; break;
        default: Bp = Wrv; Cp = g_rv; break;
    }
    gemm_body<0>(g_h, Bp, nullptr, nullptr, Cp, RR, Dd, Dd);
}

__global__ __launch_bounds__(256) void k_wo(const float* __restrict__ Wo)
{
    gemm_body<1>(g_att, Wo, g_h, nullptr, g_hres, RR, Dd, Dd);
}

__global__ __launch_bounds__(256) void k_ffn1(const float* __restrict__ W1,
                                              const float* __restrict__ b1)
{
    gemm_body<2>(g_h2, W1, nullptr, b1, g_ffn, RR, DFF, Dd);
}

__global__ __launch_bounds__(256) void k_ffn2(const float* __restrict__ W2,
                                              const float* __restrict__ b2,
                                              float* __restrict__ out)
{
    gemm_body<3>(g_ffn, W2, g_h2, b2, out, RR, Dd, DFF);
}

// ============================================================================
// Triangle attention. One block per (b, h, x); 256 threads.
// scores[a,y] = (1/sqrt(DK)) * sum_d lk[b,x,a,h,d] * rk[b,a,y,h,d]
// att = softmax over a (online);  out[y,d] = sum_a att[a,y]*lv[x,a,d]*rv[a,y,d]
// Thread t owns (y = t>>2, d-quarter dq = t&3) -> 8 accum elements in regs.
// ============================================================================
__global__ __launch_bounds__(256) void attn_kernel(const unsigned char* __restrict__ mask)
{
    const int x  = blockIdx.x;
    const int hh = blockIdx.y;
    const int b  = blockIdx.z;
    const int t  = threadIdx.x;

    __shared__ float lk_s[Nn][33];
    __shared__ float lv_s[Nn][33];
    __shared__ float rk_s[Nn][33];
    __shared__ float rv_s[Nn][33];

    // load lk[b,x,:,hh,:] and lv[b,x,:,hh,:]  (64x32 each)
    const int baseL = ((b * Nn + x) * Nn) * Dd + hh * DKk;
    for (int i = t; i < Nn * DKk; i += 256) {
        const int a = i >> 5, d = i & 31;
        lk_s[a][d] = g_lk[baseL + a * Dd + d];
        lv_s[a][d] = g_lv[baseL + a * Dd + d];
    }

    const int y  = t >> 2;
    const int dq = t & 3;

    float acc[8];
#pragma unroll
    for (int j = 0; j < 8; j++) acc[j] = 0.f;
    float m = -1e30f, l = 0.f;
    const float qk_scale = 0.17677669529663687f;   // 1/sqrt(32)
    const int maskBase = ((b * Nn + x) * Nn) * Nn; // + a*Nn + y

    for (int a = 0; a < Nn; a++) {
        __syncthreads();   // protect rk_s/rv_s reuse (also orders first lk_s use)
        const int baseR = ((b * Nn + a) * Nn) * Dd + hh * DKk;
        for (int i = t; i < Nn * DKk; i += 256) {
            const int yy = i >> 5, d = i & 31;
            rk_s[yy][d] = g_rk[baseR + yy * Dd + d];
            rv_s[yy][d] = g_rv[baseR + yy * Dd + d];
        }
        __syncthreads();

        // score: dot over d (32), split across the 4-thread group
        float part = 0.f;
#pragma unroll
        for (int j = 0; j < 8; j++)
            part += lk_s[a][dq * 8 + j] * rk_s[y][dq * 8 + j];
        part += __shfl_xor_sync(0xffffffffu, part, 1);
        part += __shfl_xor_sync(0xffffffffu, part, 2);
        float sc = part * qk_scale;
        if (mask[maskBase + a * Nn + y]) sc = -1e9f;

        // online softmax over a
        const float mn     = fmaxf(m, sc);
        const float cscale = __expf(m - mn);
        const float p      = __expf(sc - mn);
        l = l * cscale + p;
        m = mn;
#pragma unroll
        for (int j = 0; j < 8; j++)
            acc[j] = acc[j] * cscale + p * lv_s[a][dq * 8 + j] * rv_s[y][dq * 8 + j];
    }

    const float inv = 1.0f / l;
    const int outBase = ((b * Nn + x) * Nn + y) * Dd + hh * DKk + dq * 8;
    float4 v0, v1;
    v0.x = acc[0] * inv; v0.y = acc[1] * inv; v0.z = acc[2] * inv; v0.w = acc[3] * inv;
    v1.x = acc[4] * inv; v1.y = acc[5] * inv; v1.z = acc[6] * inv; v1.w = acc[7] * inv;
    *(float4*)&g_att[outBase]     = v0;
    *(float4*)&g_att[outBase + 4] = v1;
}

// ============================================================================
// launch
// ============================================================================
extern "C" void kernel_launch(void* const* d_in, const int* in_sizes, int n_in,
                              void* d_out, int out_size)
{
    const float*         x    = (const float*)d_in[0];
    const unsigned char* mask = (const unsigned char*)d_in[1];
    const float*         Wlk  = (const float*)d_in[2];
    const float*         Wrk  = (const float*)d_in[3];
    const float*         Wlv  = (const float*)d_in[4];
    const float*         Wrv  = (const float*)d_in[5];
    const float*         Wo   = (const float*)d_in[6];
    const float*         W1   = (const float*)d_in[7];
    const float*         b1   = (const float*)d_in[8];
    const float*         W2   = (const float*)d_in[9];
    const float*         b2   = (const float*)d_in[10];
    const float*         g1   = (const float*)d_in[11];
    const float*         be1  = (const float*)d_in[12];
    const float*         g2   = (const float*)d_in[13];
    const float*         be2  = (const float*)d_in[14];
    float* out = (float*)d_out;

    // 1. pre-norm
    ln1_kernel<<<RR, 256>>>(x, g1, be1);

    // 2. four projections (z selects weight/output)
    k_proj<<<dim3(Dd / 128, RR / 128, 4), 256>>>(Wlk, Wrk, Wlv, Wrv);

    // 3. triangle attention
    attn_kernel<<<dim3(Nn, Hh, Bb), 256>>>(mask);

    // 4. output projection + residual (h + att@Wo)
    k_wo<<<dim3(Dd / 128, RR / 128), 256>>>(Wo);

    // 5. LN2
    ln2_kernel<<<RR, 256>>>(g2, be2);

    // 6. FFN up (bias + relu)
    k_ffn1<<<dim3(DFF / 128, RR / 128), 256>>>(W1, b1);

    // 7. FFN down (bias + residual h2) -> out
    k_ffn2<<<dim3(Dd / 128, RR / 128), 256>>>(W2, b2, out);
}

// round 3
// speedup vs baseline: 1.2834x; 1.2834x over previous
#include <cuda_runtime.h>
#include <cstdint>

// ============================================================================
// EdgeTransformerLayer (B=2, N=64, D=256, H=8, DK=32, DFF=1024)
// GEMMs on legacy tensor-core path: mma.sync.m16n8k8 tf32 (valid on sm_100
// plain target — tcgen05 needs sm_100a which this toolchain doesn't emit).
//
// Launches:
//   0-6: transpose weights -> [N,K] K-major  (tiny)
//   7:   ln1    h = LN(x)
//   8:   proj   g_proj[8192,1024] = h @ [Wlk|Wrk|Wlv|Wrv]
//   9:   attn   triangle attention -> g_att
//   10:  wo     g_hres = g_att @ Wo + h
//   11:  ln2    h2 = LN(hres)
//   12:  ffn1   g_ffn = relu(h2 @ W1 + b1)
//   13:  ffn2   out = h2 + g_ffn @ W2 + b2
// ============================================================================

namespace {
constexpr int Bb  = 2;
constexpr int Nn  = 64;
constexpr int Dd  = 256;
constexpr int Hh  = 8;
constexpr int DKk = 32;
constexpr int DFF = 1024;
constexpr int RR  = Bb * Nn * Nn;   // 8192
constexpr int SP  = 36;             // padded SMEM row stride (floats): conflict-free frags
}

// ---- device-global scratch (no allocation allowed) --------------------------
__device__ float g_h     [RR * Dd];
__device__ float g_proj  [RR * DFF];   // cols: [0,256)=lk [256,512)=rk [512,768)=lv [768,1024)=rv
__device__ float g_att   [RR * Dd];
__device__ float g_hres  [RR * Dd];
__device__ float g_h2    [RR * Dd];
__device__ float g_ffn   [RR * DFF];
__device__ float g_Wt_qkv[DFF * Dd];   // [1024,256]
__device__ float g_Wt_o  [Dd * Dd];
__device__ float g_Wt_1  [DFF * Dd];   // W1^T [1024,256]
__device__ float g_Wt_2  [Dd * DFF];   // W2^T [256,1024]

// ============================================================================
// helpers
// ============================================================================
__device__ __forceinline__ uint32_t f2tf32(float f) {
    uint32_t r;
    asm("cvt.rna.tf32.f32 %0, %1;" : "=r"(r) : "f"(f));
    return r;
}

__device__ __forceinline__ void mma_tf32(float c[4],
                                         uint32_t a0, uint32_t a1, uint32_t a2, uint32_t a3,
                                         uint32_t b0, uint32_t b1) {
    asm volatile(
        "mma.sync.aligned.m16n8k8.row.col.f32.tf32.tf32.f32 "
        "{%0,%1,%2,%3}, {%4,%5,%6,%7}, {%8,%9}, {%0,%1,%2,%3};"
        : "+f"(c[0]), "+f"(c[1]), "+f"(c[2]), "+f"(c[3])
        : "r"(a0), "r"(a1), "r"(a2), "r"(a3), "r"(b0), "r"(b1));
}

// ============================================================================
// weight transpose: dst[n*K + k] = src[k*N + n]
// ============================================================================
__device__ __forceinline__ float* tr_dst(int which) {
    switch (which) {
        case 0: return g_Wt_qkv;
        case 1: return g_Wt_qkv + 256 * 256;
        case 2: return g_Wt_qkv + 512 * 256;
        case 3: return g_Wt_qkv + 768 * 256;
        case 4: return g_Wt_o;
        case 5: return g_Wt_1;
        default: return g_Wt_2;
    }
}

__global__ __launch_bounds__(256) void k_tr(const float* __restrict__ src,
                                            int which, int K, int N)
{
    __shared__ float tile[32][33];
    const int tx = threadIdx.x & 31;
    const int ty = threadIdx.x >> 5;
    const int n0 = blockIdx.x * 32;
    const int k0 = blockIdx.y * 32;
#pragma unroll
    for (int r = ty; r < 32; r += 8)
        tile[r][tx] = src[(k0 + r) * N + n0 + tx];
    __syncthreads();
    float* dst = tr_dst(which);
#pragma unroll
    for (int r = ty; r < 32; r += 8)
        dst[(n0 + r) * K + k0 + tx] = tile[tx][r];
}

// ============================================================================
// LayerNorm
// ============================================================================
__device__ __forceinline__ void ln_body(const float* __restrict__ in,
                                        const float* __restrict__ gam,
                                        const float* __restrict__ bet,
                                        float* __restrict__ out)
{
    const int row = blockIdx.x;
    const int t   = threadIdx.x;
    const float v = in[row * Dd + t];
    float s = v, s2 = v * v;
#pragma unroll
    for (int o = 16; o; o >>= 1) {
        s  += __shfl_xor_sync(0xffffffffu, s,  o);
        s2 += __shfl_xor_sync(0xffffffffu, s2, o);
    }
    __shared__ float ws[8], ws2[8];
    if ((t & 31) == 0) { ws[t >> 5] = s; ws2[t >> 5] = s2; }
    __syncthreads();
    float ts = 0.f, ts2 = 0.f;
#pragma unroll
    for (int i = 0; i < 8; i++) { ts += ws[i]; ts2 += ws2[i]; }
    const float mean = ts * (1.0f / Dd);
    const float var  = ts2 * (1.0f / Dd) - mean * mean;
    const float inv  = rsqrtf(var + 1e-5f);
    out[row * Dd + t] = (v - mean) * inv * gam[t] + bet[t];
}

__global__ __launch_bounds__(256) void ln1_kernel(const float* __restrict__ x,
                                                  const float* __restrict__ g1,
                                                  const float* __restrict__ be1)
{ ln_body(x, g1, be1, g_h); }

__global__ __launch_bounds__(256) void ln2_kernel(const float* __restrict__ g2,
                                                  const float* __restrict__ be2)
{ ln_body(g_hres, g2, be2, g_h2); }

// ============================================================================
// tf32 mma GEMM: C[M,NC] = A[M,K] @ Wt^T,  Wt is [NC,K] row-major.
// CTA tile 128x128, 256 threads = 8 warps (2 x 4), warp tile 64x32.
// K chunks of 32; register-prefetch double buffering; cvt to tf32 at staging.
// EPI: 0 none; 1 +Cadd; 2 +bias,relu; 3 +bias,+Cadd
// ============================================================================
template <int K, int NC, int EPI>
__device__ __forceinline__ void gemm_mma(const float* __restrict__ A,
                                         const float* __restrict__ Wt,
                                         const float* __restrict__ Cadd,
                                         const float* __restrict__ bias,
                                         float* __restrict__ C)
{
    constexpr int NCH = K / 32;
    __shared__ uint32_t As[128 * SP];
    __shared__ uint32_t Bs[128 * SP];

    const int t    = threadIdx.x;
    const int wid  = t >> 5;
    const int lane = t & 31;
    const int gr   = lane >> 2;      // 0..7
    const int tig  = lane & 3;       // 0..3
    const int wm   = (wid & 1) * 64; // warp M offset in tile
    const int wn   = (wid >> 1) * 32;

    const int bm = blockIdx.y * 128;
    const int bn = blockIdx.x * 128;

    // loader: row = t>>1 (0..127), k-base = (t&1)*16  -> 4 float4 per tile
    const int lrow = t >> 1;
    const int lk   = (t & 1) * 16;
    const float4* Ag = (const float4*)(A  + (size_t)(bm + lrow) * K + lk);
    const float4* Bg = (const float4*)(Wt + (size_t)(bn + lrow) * K + lk);

    float4 pa[4], pb[4];
#pragma unroll
    for (int i = 0; i < 4; i++) { pa[i] = Ag[i]; pb[i] = Bg[i]; }

    float acc[4][4][4];
#pragma unroll
    for (int im = 0; im < 4; im++)
#pragma unroll
        for (int in = 0; in < 4; in++)
#pragma unroll
            for (int j = 0; j < 4; j++) acc[im][in][j] = 0.f;

    uint32_t* asw = &As[lrow * SP + lk];
    uint32_t* bsw = &Bs[lrow * SP + lk];

    for (int c = 0; c < NCH; c++) {
        // stage (fp32 -> tf32) into padded SMEM
#pragma unroll
        for (int i = 0; i < 4; i++) {
            uint4 ua, ub;
            ua.x = f2tf32(pa[i].x); ua.y = f2tf32(pa[i].y);
            ua.z = f2tf32(pa[i].z); ua.w = f2tf32(pa[i].w);
            ub.x = f2tf32(pb[i].x); ub.y = f2tf32(pb[i].y);
            ub.z = f2tf32(pb[i].z); ub.w = f2tf32(pb[i].w);
            *(uint4*)(asw + i * 4) = ua;
            *(uint4*)(bsw + i * 4) = ub;
        }
        __syncthreads();

        if (c + 1 < NCH) {
#pragma unroll
            for (int i = 0; i < 4; i++) {
                pa[i] = Ag[(c + 1) * 8 + i];
                pb[i] = Bg[(c + 1) * 8 + i];
            }
        }

        // compute: 4 k-steps of 8
#pragma unroll
        for (int ks = 0; ks < 4; ks++) {
            const int k = ks * 8;
            uint32_t af[4][4], bf[4][2];
#pragma unroll
            for (int im = 0; im < 4; im++) {
                const int r0 = (wm + im * 16 + gr) * SP + k + tig;
                af[im][0] = As[r0];
                af[im][1] = As[r0 + 8 * SP];
                af[im][2] = As[r0 + 4];
                af[im][3] = As[r0 + 8 * SP + 4];
            }
#pragma unroll
            for (int in = 0; in < 4; in++) {
                const int r0 = (wn + in * 8 + gr) * SP + k + tig;
                bf[in][0] = Bs[r0];
                bf[in][1] = Bs[r0 + 4];
            }
#pragma unroll
            for (int im = 0; im < 4; im++)
#pragma unroll
                for (int in = 0; in < 4; in++)
                    mma_tf32(acc[im][in], af[im][0], af[im][1], af[im][2], af[im][3],
                             bf[in][0], bf[in][1]);
        }
        __syncthreads();
    }

    // epilogue: per mma tile, c0/c1 -> (r0, col..col+1), c2/c3 -> (r0+8, ...)
#pragma unroll
    for (int im = 0; im < 4; im++) {
        const int r0 = bm + wm + im * 16 + gr;
#pragma unroll
        for (int in = 0; in < 4; in++) {
            const int col = bn + wn + in * 8 + 2 * tig;
            float2 v0 = make_float2(acc[im][in][0], acc[im][in][1]);
            float2 v1 = make_float2(acc[im][in][2], acc[im][in][3]);
            if (EPI == 2 || EPI == 3) {
                const float2 bb = *(const float2*)&bias[col];
                v0.x += bb.x; v0.y += bb.y;
                v1.x += bb.x; v1.y += bb.y;
            }
            if (EPI == 2) {
                v0.x = fmaxf(v0.x, 0.f); v0.y = fmaxf(v0.y, 0.f);
                v1.x = fmaxf(v1.x, 0.f); v1.y = fmaxf(v1.y, 0.f);
            }
            if (EPI == 1 || EPI == 3) {
                const float2 c0 = *(const float2*)&Cadd[(size_t)r0 * NC + col];
                const float2 c1 = *(const float2*)&Cadd[(size_t)(r0 + 8) * NC + col];
                v0.x += c0.x; v0.y += c0.y;
                v1.x += c1.x; v1.y += c1.y;
            }
            *(float2*)&C[(size_t)r0 * NC + col]       = v0;
            *(float2*)&C[(size_t)(r0 + 8) * NC + col] = v1;
        }
    }
}

// ---- GEMM wrapper kernels ---------------------------------------------------
__global__ __launch_bounds__(256) void k_proj_tc()
{ gemm_mma<Dd, DFF, 0>(g_h, g_Wt_qkv, nullptr, nullptr, g_proj); }

__global__ __launch_bounds__(256) void k_wo_tc()
{ gemm_mma<Dd, Dd, 1>(g_att, g_Wt_o, g_h, nullptr, g_hres); }

__global__ __launch_bounds__(256) void k_ffn1_tc(const float* __restrict__ b1)
{ gemm_mma<Dd, DFF, 2>(g_h2, g_Wt_1, nullptr, b1, g_ffn); }

__global__ __launch_bounds__(256) void k_ffn2_tc(const float* __restrict__ b2,
                                                 float* __restrict__ out)
{ gemm_mma<DFF, Dd, 3>(g_ffn, g_Wt_2, g_h2, b2, out); }

// ============================================================================
// Triangle attention. One block per (b, h, x); 256 threads.
// Reads lk/rk/lv/rv from fused g_proj (stride 1024; col offsets 0/256/512/768).
// ============================================================================
__global__ __launch_bounds__(256) void attn_kernel(const unsigned char* __restrict__ mask)
{
    const int x  = blockIdx.x;
    const int hh = blockIdx.y;
    const int b  = blockIdx.z;
    const int t  = threadIdx.x;

    __shared__ float lk_s[Nn][33];
    __shared__ float lv_s[Nn][33];
    __shared__ float rk_s[Nn][33];
    __shared__ float rv_s[Nn][33];

    const int baseL = ((b * Nn + x) * Nn) * DFF + hh * DKk;
    for (int i = t; i < Nn * DKk; i += 256) {
        const int a = i >> 5, d = i & 31;
        lk_s[a][d] = g_proj[baseL + a * DFF + 0   + d];
        lv_s[a][d] = g_proj[baseL + a * DFF + 512 + d];
    }

    const int y  = t >> 2;
    const int dq = t & 3;

    float acc[8];
#pragma unroll
    for (int j = 0; j < 8; j++) acc[j] = 0.f;
    float m = -1e30f, l = 0.f;
    const float qk_scale = 0.17677669529663687f;   // 1/sqrt(32)
    const int maskBase = ((b * Nn + x) * Nn) * Nn;

    for (int a = 0; a < Nn; a++) {
        __syncthreads();
        const int baseR = ((b * Nn + a) * Nn) * DFF + hh * DKk;
        for (int i = t; i < Nn * DKk; i += 256) {
            const int yy = i >> 5, d = i & 31;
            rk_s[yy][d] = g_proj[baseR + yy * DFF + 256 + d];
            rv_s[yy][d] = g_proj[baseR + yy * DFF + 768 + d];
        }
        __syncthreads();

        float part = 0.f;
#pragma unroll
        for (int j = 0; j < 8; j++)
            part += lk_s[a][dq * 8 + j] * rk_s[y][dq * 8 + j];
        part += __shfl_xor_sync(0xffffffffu, part, 1);
        part += __shfl_xor_sync(0xffffffffu, part, 2);
        float sc = part * qk_scale;
        if (mask[maskBase + a * Nn + y]) sc = -1e9f;

        const float mn     = fmaxf(m, sc);
        const float cscale = __expf(m - mn);
        const float p      = __expf(sc - mn);
        l = l * cscale + p;
        m = mn;
#pragma unroll
        for (int j = 0; j < 8; j++)
            acc[j] = acc[j] * cscale + p * lv_s[a][dq * 8 + j] * rv_s[y][dq * 8 + j];
    }

    const float inv = 1.0f / l;
    const int outBase = ((b * Nn + x) * Nn + y) * Dd + hh * DKk + dq * 8;
    float4 v0, v1;
    v0.x = acc[0] * inv; v0.y = acc[1] * inv; v0.z = acc[2] * inv; v0.w = acc[3] * inv;
    v1.x = acc[4] * inv; v1.y = acc[5] * inv; v1.z = acc[6] * inv; v1.w = acc[7] * inv;
    *(float4*)&g_att[outBase]     = v0;
    *(float4*)&g_att[outBase + 4] = v1;
}

// ============================================================================
// launch
// ============================================================================
extern "C" void kernel_launch(void* const* d_in, const int* in_sizes, int n_in,
                              void* d_out, int out_size)
{
    const float*         x    = (const float*)d_in[0];
    const unsigned char* mask = (const unsigned char*)d_in[1];
    const float*         Wlk  = (const float*)d_in[2];
    const float*         Wrk  = (const float*)d_in[3];
    const float*         Wlv  = (const float*)d_in[4];
    const float*         Wrv  = (const float*)d_in[5];
    const float*         Wo   = (const float*)d_in[6];
    const float*         W1   = (const float*)d_in[7];
    const float*         b1   = (const float*)d_in[8];
    const float*         W2   = (const float*)d_in[9];
    const float*         b2   = (const float*)d_in[10];
    const float*         g1   = (const float*)d_in[11];
    const float*         be1  = (const float*)d_in[12];
    const float*         g2   = (const float*)d_in[13];
    const float*         be2  = (const float*)d_in[14];
    float* out = (float*)d_out;

    // weight transposes -> [N,K] K-major
    k_tr<<<dim3(8, 8),  256>>>(Wlk, 0, Dd, Dd);
    k_tr<<<dim3(8, 8),  256>>>(Wrk, 1, Dd, Dd);
    k_tr<<<dim3(8, 8),  256>>>(Wlv, 2, Dd, Dd);
    k_tr<<<dim3(8, 8),  256>>>(Wrv, 3, Dd, Dd);
    k_tr<<<dim3(8, 8),  256>>>(Wo,  4, Dd, Dd);
    k_tr<<<dim3(32, 8), 256>>>(W1,  5, Dd, DFF);
    k_tr<<<dim3(8, 32), 256>>>(W2,  6, DFF, Dd);

    // 1. pre-norm
    ln1_kernel<<<RR, 256>>>(x, g1, be1);

    // 2. fused projections
    k_proj_tc<<<dim3(DFF / 128, RR / 128), 256>>>();

    // 3. triangle attention
    attn_kernel<<<dim3(Nn, Hh, Bb), 256>>>(mask);

    // 4. output projection + residual
    k_wo_tc<<<dim3(Dd / 128, RR / 128), 256>>>();

    // 5. LN2
    ln2_kernel<<<RR, 256>>>(g2, be2);

    // 6. FFN up
    k_ffn1_tc<<<dim3(DFF / 128, RR / 128), 256>>>(b1);

    // 7. FFN down -> out
    k_ffn2_tc<<<dim3(Dd / 128, RR / 128), 256>>>(b2, out);
}

// round 4
// speedup vs baseline: 2.1912x; 1.7073x over previous
#include <cuda_runtime.h>
#include <cstdint>

// ============================================================================
// EdgeTransformerLayer (B=2, N=64, D=256, H=8, DK=32, DFF=1024)
// GEMMs: mma.sync.m16n8k8 tf32 + ldmatrix fragment loads (plain sm_100 path).
// Attention: x-tiled (8x) to cut L2 traffic 8x.
// 8 launches total.
// ============================================================================

namespace {
constexpr int Bb  = 2;
constexpr int Nn  = 64;
constexpr int Dd  = 256;
constexpr int Hh  = 8;
constexpr int DKk = 32;
constexpr int DFF = 1024;
constexpr int RR  = Bb * Nn * Nn;   // 8192
constexpr int SP  = 36;             // padded SMEM row stride (floats)
constexpr int TX  = 8;              // attention x-tile
}

// ---- device-global scratch (no allocation allowed) --------------------------
__device__ float g_h     [RR * Dd];
__device__ float g_proj  [RR * DFF];   // cols: [0,256)=lk [256,512)=rk [512,768)=lv [768,1024)=rv
__device__ float g_att   [RR * Dd];
__device__ float g_hres  [RR * Dd];
__device__ float g_h2    [RR * Dd];
__device__ float g_ffn   [RR * DFF];
__device__ float g_Wt_qkv[DFF * Dd];   // [1024,256]
__device__ float g_Wt_o  [Dd * Dd];
__device__ float g_Wt_1  [DFF * Dd];   // W1^T [1024,256]
__device__ float g_Wt_2  [Dd * DFF];   // W2^T [256,1024]

// ============================================================================
// helpers
// ============================================================================
__device__ __forceinline__ uint32_t smem_u32(const void* p) {
    uint32_t a;
    asm("{ .reg .u64 t; cvta.to.shared.u64 t, %1; cvt.u32.u64 %0, t; }" : "=r"(a) : "l"(p));
    return a;
}

__device__ __forceinline__ uint32_t f2tf32(float f) {
    uint32_t r;
    asm("cvt.rna.tf32.f32 %0, %1;" : "=r"(r) : "f"(f));
    return r;
}

__device__ __forceinline__ void mma_tf32(float c[4],
                                         uint32_t a0, uint32_t a1, uint32_t a2, uint32_t a3,
                                         uint32_t b0, uint32_t b1) {
    asm volatile(
        "mma.sync.aligned.m16n8k8.row.col.f32.tf32.tf32.f32 "
        "{%0,%1,%2,%3}, {%4,%5,%6,%7}, {%8,%9}, {%0,%1,%2,%3};"
        : "+f"(c[0]), "+f"(c[1]), "+f"(c[2]), "+f"(c[3])
        : "r"(a0), "r"(a1), "r"(a2), "r"(a3), "r"(b0), "r"(b1));
}

__device__ __forceinline__ void ldsm_x4(uint32_t r[4], uint32_t addr) {
    asm volatile("ldmatrix.sync.aligned.m8n8.x4.shared.b16 {%0,%1,%2,%3}, [%4];"
                 : "=r"(r[0]), "=r"(r[1]), "=r"(r[2]), "=r"(r[3]) : "r"(addr));
}
__device__ __forceinline__ void ldsm_x2(uint32_t r[2], uint32_t addr) {
    asm volatile("ldmatrix.sync.aligned.m8n8.x2.shared.b16 {%0,%1}, [%2];"
                 : "=r"(r[0]), "=r"(r[1]) : "r"(addr));
}

// ============================================================================
// fused weight transposes: dst[n*K + k] = src[k*N + n]; one launch, 832 tiles
// ============================================================================
__global__ __launch_bounds__(256) void k_tr_all(const float* __restrict__ Wlk,
                                                const float* __restrict__ Wrk,
                                                const float* __restrict__ Wlv,
                                                const float* __restrict__ Wrv,
                                                const float* __restrict__ Wo,
                                                const float* __restrict__ W1,
                                                const float* __restrict__ W2)
{
    __shared__ float tile[32][33];
    const int id = blockIdx.x;
    const float* src;
    float* dst;
    int K, N, n0, k0;
    if (id < 320) {
        const int w = id >> 6;
        const int tl = id & 63;
        src = (w == 0) ? Wlk : (w == 1) ? Wrk : (w == 2) ? Wlv : (w == 3) ? Wrv : Wo;
        dst = (w < 4) ? (g_Wt_qkv + w * 256 * 256) : g_Wt_o;
        K = 256; N = 256;
        n0 = (tl & 7) * 32; k0 = (tl >> 3) * 32;
    } else if (id < 576) {
        const int tl = id - 320;
        src = W1; dst = g_Wt_1; K = 256; N = 1024;
        n0 = (tl & 31) * 32; k0 = (tl >> 5) * 32;
    } else {
        const int tl = id - 576;
        src = W2; dst = g_Wt_2; K = 1024; N = 256;
        n0 = (tl & 7) * 32; k0 = (tl >> 3) * 32;
    }
    const int tx = threadIdx.x & 31;
    const int ty = threadIdx.x >> 5;
#pragma unroll
    for (int r = ty; r < 32; r += 8)
        tile[r][tx] = src[(size_t)(k0 + r) * N + n0 + tx];
    __syncthreads();
#pragma unroll
    for (int r = ty; r < 32; r += 8)
        dst[(size_t)(n0 + r) * K + k0 + tx] = tile[tx][r];
}

// ============================================================================
// LayerNorm
// ============================================================================
__device__ __forceinline__ void ln_body(const float* __restrict__ in,
                                        const float* __restrict__ gam,
                                        const float* __restrict__ bet,
                                        float* __restrict__ out)
{
    const int row = blockIdx.x;
    const int t   = threadIdx.x;
    const float v = in[row * Dd + t];
    float s = v, s2 = v * v;
#pragma unroll
    for (int o = 16; o; o >>= 1) {
        s  += __shfl_xor_sync(0xffffffffu, s,  o);
        s2 += __shfl_xor_sync(0xffffffffu, s2, o);
    }
    __shared__ float ws[8], ws2[8];
    if ((t & 31) == 0) { ws[t >> 5] = s; ws2[t >> 5] = s2; }
    __syncthreads();
    float ts = 0.f, ts2 = 0.f;
#pragma unroll
    for (int i = 0; i < 8; i++) { ts += ws[i]; ts2 += ws2[i]; }
    const float mean = ts * (1.0f / Dd);
    const float var  = ts2 * (1.0f / Dd) - mean * mean;
    const float inv  = rsqrtf(var + 1e-5f);
    out[row * Dd + t] = (v - mean) * inv * gam[t] + bet[t];
}

__global__ __launch_bounds__(256) void ln1_kernel(const float* __restrict__ x,
                                                  const float* __restrict__ g1,
                                                  const float* __restrict__ be1)
{ ln_body(x, g1, be1, g_h); }

__global__ __launch_bounds__(256) void ln2_kernel(const float* __restrict__ g2,
                                                  const float* __restrict__ be2)
{ ln_body(g_hres, g2, be2, g_h2); }

// ============================================================================
// tf32 mma GEMM: C[M,NC] = A[M,K] @ Wt^T,  Wt is [NC,K] row-major.
// CTA 128x128, 256 threads (8 warps, 2x4), warp tile 64x32, K chunks of 32.
// Fragments via ldmatrix (conflict-free with SP=36). EPI as before.
// ============================================================================
template <int K, int NC, int EPI>
__device__ __forceinline__ void gemm_mma(const float* __restrict__ A,
                                         const float* __restrict__ Wt,
                                         const float* __restrict__ Cadd,
                                         const float* __restrict__ bias,
                                         float* __restrict__ C)
{
    constexpr int NCH = K / 32;
    __shared__ alignas(16) uint32_t As[128 * SP];
    __shared__ alignas(16) uint32_t Bs[128 * SP];

    const int t    = threadIdx.x;
    const int lane = t & 31;
    const int wid  = t >> 5;
    const int gr   = lane >> 2;
    const int tig  = lane & 3;
    const int wm   = (wid & 1) * 64;
    const int wn   = (wid >> 1) * 32;

    const int bm = blockIdx.y * 128;
    const int bn = blockIdx.x * 128;

    // ldmatrix per-lane base addresses (bytes)
    const uint32_t as_base = smem_u32(As);
    const uint32_t bs_base = smem_u32(Bs);
    const uint32_t a_addr0 = as_base + ((wm + (lane & 15)) * SP + ((lane >> 4) & 1) * 4) * 4;
    const uint32_t b_addr0 = bs_base + ((wn + (lane & 7)) * SP + ((lane >> 3) & 1) * 4) * 4;

    // staging: row = t>>1, k-base = (t&1)*16
    const int lrow = t >> 1;
    const int lk   = (t & 1) * 16;
    const float4* Ag = (const float4*)(A  + (size_t)(bm + lrow) * K + lk);
    const float4* Bg = (const float4*)(Wt + (size_t)(bn + lrow) * K + lk);

    float4 pa[4], pb[4];
#pragma unroll
    for (int i = 0; i < 4; i++) { pa[i] = Ag[i]; pb[i] = Bg[i]; }

    float acc[4][4][4];
#pragma unroll
    for (int im = 0; im < 4; im++)
#pragma unroll
        for (int in = 0; in < 4; in++)
#pragma unroll
            for (int j = 0; j < 4; j++) acc[im][in][j] = 0.f;

    uint32_t* asw = &As[lrow * SP + lk];
    uint32_t* bsw = &Bs[lrow * SP + lk];

    for (int c = 0; c < NCH; c++) {
#pragma unroll
        for (int i = 0; i < 4; i++) {
            uint4 ua, ub;
            ua.x = f2tf32(pa[i].x); ua.y = f2tf32(pa[i].y);
            ua.z = f2tf32(pa[i].z); ua.w = f2tf32(pa[i].w);
            ub.x = f2tf32(pb[i].x); ub.y = f2tf32(pb[i].y);
            ub.z = f2tf32(pb[i].z); ub.w = f2tf32(pb[i].w);
            *(uint4*)(asw + i * 4) = ua;
            *(uint4*)(bsw + i * 4) = ub;
        }
        __syncthreads();

        if (c + 1 < NCH) {
#pragma unroll
            for (int i = 0; i < 4; i++) {
                pa[i] = Ag[(c + 1) * 8 + i];
                pb[i] = Bg[(c + 1) * 8 + i];
            }
        }

#pragma unroll
        for (int ks = 0; ks < 4; ks++) {
            uint32_t af[4][4], bf[4][2];
#pragma unroll
            for (int im = 0; im < 4; im++)
                ldsm_x4(af[im], a_addr0 + (uint32_t)(im * 16 * SP * 4 + ks * 32));
#pragma unroll
            for (int in = 0; in < 4; in++)
                ldsm_x2(bf[in], b_addr0 + (uint32_t)(in * 8 * SP * 4 + ks * 32));
#pragma unroll
            for (int im = 0; im < 4; im++)
#pragma unroll
                for (int in = 0; in < 4; in++)
                    mma_tf32(acc[im][in], af[im][0], af[im][1], af[im][2], af[im][3],
                             bf[in][0], bf[in][1]);
        }
        __syncthreads();
    }

    // epilogue
#pragma unroll
    for (int im = 0; im < 4; im++) {
        const int r0 = bm + wm + im * 16 + gr;
#pragma unroll
        for (int in = 0; in < 4; in++) {
            const int col = bn + wn + in * 8 + 2 * tig;
            float2 v0 = make_float2(acc[im][in][0], acc[im][in][1]);
            float2 v1 = make_float2(acc[im][in][2], acc[im][in][3]);
            if (EPI == 2 || EPI == 3) {
                const float2 bb = *(const float2*)&bias[col];
                v0.x += bb.x; v0.y += bb.y;
                v1.x += bb.x; v1.y += bb.y;
            }
            if (EPI == 2) {
                v0.x = fmaxf(v0.x, 0.f); v0.y = fmaxf(v0.y, 0.f);
                v1.x = fmaxf(v1.x, 0.f); v1.y = fmaxf(v1.y, 0.f);
            }
            if (EPI == 1 || EPI == 3) {
                const float2 c0 = *(const float2*)&Cadd[(size_t)r0 * NC + col];
                const float2 c1 = *(const float2*)&Cadd[(size_t)(r0 + 8) * NC + col];
                v0.x += c0.x; v0.y += c0.y;
                v1.x += c1.x; v1.y += c1.y;
            }
            *(float2*)&C[(size_t)r0 * NC + col]       = v0;
            *(float2*)&C[(size_t)(r0 + 8) * NC + col] = v1;
        }
    }
}

// ---- GEMM wrapper kernels ---------------------------------------------------
__global__ __launch_bounds__(256) void k_proj_tc()
{ gemm_mma<Dd, DFF, 0>(g_h, g_Wt_qkv, nullptr, nullptr, g_proj); }

__global__ __launch_bounds__(256) void k_wo_tc()
{ gemm_mma<Dd, Dd, 1>(g_att, g_Wt_o, g_h, nullptr, g_hres); }

__global__ __launch_bounds__(256) void k_ffn1_tc(const float* __restrict__ b1)
{ gemm_mma<Dd, DFF, 2>(g_h2, g_Wt_1, nullptr, b1, g_ffn); }

__global__ __launch_bounds__(256) void k_ffn2_tc(const float* __restrict__ b2,
                                                 float* __restrict__ out)
{ gemm_mma<DFF, Dd, 3>(g_ffn, g_Wt_2, g_h2, b2, out); }

// ============================================================================
// Triangle attention v2 — x-tiled. Block = (x-tile of 8, h, b); 256 threads.
// rk/rv loaded once per a per x-tile (8x less L2 traffic than per-x blocks).
// Thread owns (y = t>>2, dq = t&3); acc[TX][8] in registers.
// ============================================================================
__global__ __launch_bounds__(256) void attn2_kernel(const unsigned char* __restrict__ mask)
{
    const int xt = blockIdx.x;      // 0..7
    const int hh = blockIdx.y;
    const int b  = blockIdx.z;
    const int t  = threadIdx.x;
    const int y  = t >> 2;
    const int dq = t & 3;
    const int x0 = xt * TX;

    __shared__ float rk_s[Nn][36];
    __shared__ float rv_s[Nn][36];
    __shared__ float lk_s[TX][36];
    __shared__ float lv_s[TX][36];

    float acc[TX][8];
    float m[TX], l[TX];
#pragma unroll
    for (int xx = 0; xx < TX; xx++) {
        m[xx] = -1e30f; l[xx] = 0.f;
#pragma unroll
        for (int j = 0; j < 8; j++) acc[xx][j] = 0.f;
    }

    const float qk_scale = 0.17677669529663687f;   // 1/sqrt(32)

    for (int a = 0; a < Nn; a++) {
        __syncthreads();
        const int baseR = ((b * Nn + a) * Nn) * DFF + hh * DKk;
#pragma unroll
        for (int u = t; u < 512; u += 256) {
            const int row = u >> 3, c4 = (u & 7) * 4;
            *(float4*)&rk_s[row][c4] = *(const float4*)&g_proj[baseR + row * DFF + 256 + c4];
            *(float4*)&rv_s[row][c4] = *(const float4*)&g_proj[baseR + row * DFF + 768 + c4];
        }
        if (t < 64) {
            const int xr = t >> 3, c4 = (t & 7) * 4;
            const int baseL = ((b * Nn + x0 + xr) * Nn + a) * DFF + hh * DKk;
            *(float4*)&lk_s[xr][c4] = *(const float4*)&g_proj[baseL + c4];
            *(float4*)&lv_s[xr][c4] = *(const float4*)&g_proj[baseL + 512 + c4];
        }
        __syncthreads();

        const float4 rk0 = *(const float4*)&rk_s[y][dq * 8];
        const float4 rk1 = *(const float4*)&rk_s[y][dq * 8 + 4];
        const float4 rv0 = *(const float4*)&rv_s[y][dq * 8];
        const float4 rv1 = *(const float4*)&rv_s[y][dq * 8 + 4];
        const int maskBase = ((b * Nn + x0) * Nn + a) * Nn + y;   // + xx*Nn*Nn

#pragma unroll
        for (int xx = 0; xx < TX; xx++) {
            const float4 lk0 = *(const float4*)&lk_s[xx][dq * 8];
            const float4 lk1 = *(const float4*)&lk_s[xx][dq * 8 + 4];
            float part = lk0.x * rk0.x + lk0.y * rk0.y + lk0.z * rk0.z + lk0.w * rk0.w
                       + lk1.x * rk1.x + lk1.y * rk1.y + lk1.z * rk1.z + lk1.w * rk1.w;
            part += __shfl_xor_sync(0xffffffffu, part, 1);
            part += __shfl_xor_sync(0xffffffffu, part, 2);
            float sc = part * qk_scale;
            if (mask[maskBase + xx * Nn * Nn]) sc = -1e9f;

            const float mn = fmaxf(m[xx], sc);
            const float cs = __expf(m[xx] - mn);
            const float p  = __expf(sc - mn);
            l[xx] = l[xx] * cs + p;
            m[xx] = mn;

            const float4 lv0 = *(const float4*)&lv_s[xx][dq * 8];
            const float4 lv1 = *(const float4*)&lv_s[xx][dq * 8 + 4];
            acc[xx][0] = acc[xx][0] * cs + p * lv0.x * rv0.x;
            acc[xx][1] = acc[xx][1] * cs + p * lv0.y * rv0.y;
            acc[xx][2] = acc[xx][2] * cs + p * lv0.z * rv0.z;
            acc[xx][3] = acc[xx][3] * cs + p * lv0.w * rv0.w;
            acc[xx][4] = acc[xx][4] * cs + p * lv1.x * rv1.x;
            acc[xx][5] = acc[xx][5] * cs + p * lv1.y * rv1.y;
            acc[xx][6] = acc[xx][6] * cs + p * lv1.z * rv1.z;
            acc[xx][7] = acc[xx][7] * cs + p * lv1.w * rv1.w;
        }
    }

#pragma unroll
    for (int xx = 0; xx < TX; xx++) {
        const float inv = 1.0f / l[xx];
        const int ob = ((b * Nn + x0 + xx) * Nn + y) * Dd + hh * DKk + dq * 8;
        float4 v0, v1;
        v0.x = acc[xx][0] * inv; v0.y = acc[xx][1] * inv;
        v0.z = acc[xx][2] * inv; v0.w = acc[xx][3] * inv;
        v1.x = acc[xx][4] * inv; v1.y = acc[xx][5] * inv;
        v1.z = acc[xx][6] * inv; v1.w = acc[xx][7] * inv;
        *(float4*)&g_att[ob]     = v0;
        *(float4*)&g_att[ob + 4] = v1;
    }
}

// ============================================================================
// launch
// ============================================================================
extern "C" void kernel_launch(void* const* d_in, const int* in_sizes, int n_in,
                              void* d_out, int out_size)
{
    const float*         x    = (const float*)d_in[0];
    const unsigned char* mask = (const unsigned char*)d_in[1];
    const float*         Wlk  = (const float*)d_in[2];
    const float*         Wrk  = (const float*)d_in[3];
    const float*         Wlv  = (const float*)d_in[4];
    const float*         Wrv  = (const float*)d_in[5];
    const float*         Wo   = (const float*)d_in[6];
    const float*         W1   = (const float*)d_in[7];
    const float*         b1   = (const float*)d_in[8];
    const float*         W2   = (const float*)d_in[9];
    const float*         b2   = (const float*)d_in[10];
    const float*         g1   = (const float*)d_in[11];
    const float*         be1  = (const float*)d_in[12];
    const float*         g2   = (const float*)d_in[13];
    const float*         be2  = (const float*)d_in[14];
    float* out = (float*)d_out;

    // 0. all weight transposes in one launch
    k_tr_all<<<832, 256>>>(Wlk, Wrk, Wlv, Wrv, Wo, W1, W2);

    // 1. pre-norm
    ln1_kernel<<<RR, 256>>>(x, g1, be1);

    // 2. fused projections
    k_proj_tc<<<dim3(DFF / 128, RR / 128), 256>>>();

    // 3. triangle attention (x-tiled)
    attn2_kernel<<<dim3(Nn / TX, Hh, Bb), 256>>>(mask);

    // 4. output projection + residual
    k_wo_tc<<<dim3(Dd / 128, RR / 128), 256>>>();

    // 5. LN2
    ln2_kernel<<<RR, 256>>>(g2, be2);

    // 6. FFN up
    k_ffn1_tc<<<dim3(DFF / 128, RR / 128), 256>>>(b1);

    // 7. FFN down -> out
    k_ffn2_tc<<<dim3(Dd / 128, RR / 128), 256>>>(b2, out);
}

// round 5
// speedup vs baseline: 2.4786x; 1.1312x over previous
#include <cuda_runtime.h>
#include <cstdint>

// ============================================================================
// EdgeTransformerLayer (B=2, N=64, D=256, H=8, DK=32, DFF=1024)
// GEMMs: mma.sync.m16n8k8 tf32 + ldmatrix (plain sm_100 path).
// Attention: x-tiled + double-buffered SMEM pipeline (1 barrier / a-step).
// ============================================================================

namespace {
constexpr int Bb  = 2;
constexpr int Nn  = 64;
constexpr int Dd  = 256;
constexpr int Hh  = 8;
constexpr int DKk = 32;
constexpr int DFF = 1024;
constexpr int RR  = Bb * Nn * Nn;   // 8192
constexpr int SP  = 36;             // padded SMEM row stride (floats)
constexpr int TX  = 8;              // attention x-tile
}

// ---- device-global scratch (no allocation allowed) --------------------------
__device__ float g_h     [RR * Dd];
__device__ float g_proj  [RR * DFF];   // cols: [0,256)=lk [256,512)=rk [512,768)=lv [768,1024)=rv
__device__ float g_att   [RR * Dd];
__device__ float g_hres  [RR * Dd];
__device__ float g_h2    [RR * Dd];
__device__ float g_ffn   [RR * DFF];
__device__ float g_Wt_qkv[DFF * Dd];   // [1024,256]
__device__ float g_Wt_o  [Dd * Dd];
__device__ float g_Wt_1  [DFF * Dd];   // W1^T [1024,256]
__device__ float g_Wt_2  [Dd * DFF];   // W2^T [256,1024]

// ============================================================================
// helpers
// ============================================================================
__device__ __forceinline__ uint32_t smem_u32(const void* p) {
    uint32_t a;
    asm("{ .reg .u64 t; cvta.to.shared.u64 t, %1; cvt.u32.u64 %0, t; }" : "=r"(a) : "l"(p));
    return a;
}

__device__ __forceinline__ uint32_t f2tf32(float f) {
    uint32_t r;
    asm("cvt.rna.tf32.f32 %0, %1;" : "=r"(r) : "f"(f));
    return r;
}

__device__ __forceinline__ void mma_tf32(float c[4],
                                         uint32_t a0, uint32_t a1, uint32_t a2, uint32_t a3,
                                         uint32_t b0, uint32_t b1) {
    asm volatile(
        "mma.sync.aligned.m16n8k8.row.col.f32.tf32.tf32.f32 "
        "{%0,%1,%2,%3}, {%4,%5,%6,%7}, {%8,%9}, {%0,%1,%2,%3};"
        : "+f"(c[0]), "+f"(c[1]), "+f"(c[2]), "+f"(c[3])
        : "r"(a0), "r"(a1), "r"(a2), "r"(a3), "r"(b0), "r"(b1));
}

__device__ __forceinline__ void ldsm_x4(uint32_t r[4], uint32_t addr) {
    asm volatile("ldmatrix.sync.aligned.m8n8.x4.shared.b16 {%0,%1,%2,%3}, [%4];"
                 : "=r"(r[0]), "=r"(r[1]), "=r"(r[2]), "=r"(r[3]) : "r"(addr));
}
__device__ __forceinline__ void ldsm_x2(uint32_t r[2], uint32_t addr) {
    asm volatile("ldmatrix.sync.aligned.m8n8.x2.shared.b16 {%0,%1}, [%2];"
                 : "=r"(r[0]), "=r"(r[1]) : "r"(addr));
}

// ============================================================================
// fused weight transposes: dst[n*K + k] = src[k*N + n]; one launch, 832 tiles
// ============================================================================
__global__ __launch_bounds__(256) void k_tr_all(const float* __restrict__ Wlk,
                                                const float* __restrict__ Wrk,
                                                const float* __restrict__ Wlv,
                                                const float* __restrict__ Wrv,
                                                const float* __restrict__ Wo,
                                                const float* __restrict__ W1,
                                                const float* __restrict__ W2)
{
    __shared__ float tile[32][33];
    const int id = blockIdx.x;
    const float* src;
    float* dst;
    int K, N, n0, k0;
    if (id < 320) {
        const int w = id >> 6;
        const int tl = id & 63;
        src = (w == 0) ? Wlk : (w == 1) ? Wrk : (w == 2) ? Wlv : (w == 3) ? Wrv : Wo;
        dst = (w < 4) ? (g_Wt_qkv + w * 256 * 256) : g_Wt_o;
        K = 256; N = 256;
        n0 = (tl & 7) * 32; k0 = (tl >> 3) * 32;
    } else if (id < 576) {
        const int tl = id - 320;
        src = W1; dst = g_Wt_1; K = 256; N = 1024;
        n0 = (tl & 31) * 32; k0 = (tl >> 5) * 32;
    } else {
        const int tl = id - 576;
        src = W2; dst = g_Wt_2; K = 1024; N = 256;
        n0 = (tl & 7) * 32; k0 = (tl >> 3) * 32;
    }
    const int tx = threadIdx.x & 31;
    const int ty = threadIdx.x >> 5;
#pragma unroll
    for (int r = ty; r < 32; r += 8)
        tile[r][tx] = src[(size_t)(k0 + r) * N + n0 + tx];
    __syncthreads();
#pragma unroll
    for (int r = ty; r < 32; r += 8)
        dst[(size_t)(n0 + r) * K + k0 + tx] = tile[tx][r];
}

// ============================================================================
// LayerNorm
// ============================================================================
__device__ __forceinline__ void ln_body(const float* __restrict__ in,
                                        const float* __restrict__ gam,
                                        const float* __restrict__ bet,
                                        float* __restrict__ out)
{
    const int row = blockIdx.x;
    const int t   = threadIdx.x;
    const float v = in[row * Dd + t];
    float s = v, s2 = v * v;
#pragma unroll
    for (int o = 16; o; o >>= 1) {
        s  += __shfl_xor_sync(0xffffffffu, s,  o);
        s2 += __shfl_xor_sync(0xffffffffu, s2, o);
    }
    __shared__ float ws[8], ws2[8];
    if ((t & 31) == 0) { ws[t >> 5] = s; ws2[t >> 5] = s2; }
    __syncthreads();
    float ts = 0.f, ts2 = 0.f;
#pragma unroll
    for (int i = 0; i < 8; i++) { ts += ws[i]; ts2 += ws2[i]; }
    const float mean = ts * (1.0f / Dd);
    const float var  = ts2 * (1.0f / Dd) - mean * mean;
    const float inv  = rsqrtf(var + 1e-5f);
    out[row * Dd + t] = (v - mean) * inv * gam[t] + bet[t];
}

__global__ __launch_bounds__(256) void ln1_kernel(const float* __restrict__ x,
                                                  const float* __restrict__ g1,
                                                  const float* __restrict__ be1)
{ ln_body(x, g1, be1, g_h); }

__global__ __launch_bounds__(256) void ln2_kernel(const float* __restrict__ g2,
                                                  const float* __restrict__ be2)
{ ln_body(g_hres, g2, be2, g_h2); }

// ============================================================================
// tf32 mma GEMM (unchanged from round 4): CTA 128x128, 8 warps, ldmatrix frags
// ============================================================================
template <int K, int NC, int EPI>
__device__ __forceinline__ void gemm_mma(const float* __restrict__ A,
                                         const float* __restrict__ Wt,
                                         const float* __restrict__ Cadd,
                                         const float* __restrict__ bias,
                                         float* __restrict__ C)
{
    constexpr int NCH = K / 32;
    __shared__ alignas(16) uint32_t As[128 * SP];
    __shared__ alignas(16) uint32_t Bs[128 * SP];

    const int t    = threadIdx.x;
    const int lane = t & 31;
    const int wid  = t >> 5;
    const int gr   = lane >> 2;
    const int tig  = lane & 3;
    const int wm   = (wid & 1) * 64;
    const int wn   = (wid >> 1) * 32;

    const int bm = blockIdx.y * 128;
    const int bn = blockIdx.x * 128;

    const uint32_t as_base = smem_u32(As);
    const uint32_t bs_base = smem_u32(Bs);
    const uint32_t a_addr0 = as_base + ((wm + (lane & 15)) * SP + ((lane >> 4) & 1) * 4) * 4;
    const uint32_t b_addr0 = bs_base + ((wn + (lane & 7)) * SP + ((lane >> 3) & 1) * 4) * 4;

    const int lrow = t >> 1;
    const int lk   = (t & 1) * 16;
    const float4* Ag = (const float4*)(A  + (size_t)(bm + lrow) * K + lk);
    const float4* Bg = (const float4*)(Wt + (size_t)(bn + lrow) * K + lk);

    float4 pa[4], pb[4];
#pragma unroll
    for (int i = 0; i < 4; i++) { pa[i] = Ag[i]; pb[i] = Bg[i]; }

    float acc[4][4][4];
#pragma unroll
    for (int im = 0; im < 4; im++)
#pragma unroll
        for (int in = 0; in < 4; in++)
#pragma unroll
            for (int j = 0; j < 4; j++) acc[im][in][j] = 0.f;

    uint32_t* asw = &As[lrow * SP + lk];
    uint32_t* bsw = &Bs[lrow * SP + lk];

    for (int c = 0; c < NCH; c++) {
#pragma unroll
        for (int i = 0; i < 4; i++) {
            uint4 ua, ub;
            ua.x = f2tf32(pa[i].x); ua.y = f2tf32(pa[i].y);
            ua.z = f2tf32(pa[i].z); ua.w = f2tf32(pa[i].w);
            ub.x = f2tf32(pb[i].x); ub.y = f2tf32(pb[i].y);
            ub.z = f2tf32(pb[i].z); ub.w = f2tf32(pb[i].w);
            *(uint4*)(asw + i * 4) = ua;
            *(uint4*)(bsw + i * 4) = ub;
        }
        __syncthreads();

        if (c + 1 < NCH) {
#pragma unroll
            for (int i = 0; i < 4; i++) {
                pa[i] = Ag[(c + 1) * 8 + i];
                pb[i] = Bg[(c + 1) * 8 + i];
            }
        }

#pragma unroll
        for (int ks = 0; ks < 4; ks++) {
            uint32_t af[4][4], bf[4][2];
#pragma unroll
            for (int im = 0; im < 4; im++)
                ldsm_x4(af[im], a_addr0 + (uint32_t)(im * 16 * SP * 4 + ks * 32));
#pragma unroll
            for (int in = 0; in < 4; in++)
                ldsm_x2(bf[in], b_addr0 + (uint32_t)(in * 8 * SP * 4 + ks * 32));
#pragma unroll
            for (int im = 0; im < 4; im++)
#pragma unroll
                for (int in = 0; in < 4; in++)
                    mma_tf32(acc[im][in], af[im][0], af[im][1], af[im][2], af[im][3],
                             bf[in][0], bf[in][1]);
        }
        __syncthreads();
    }

#pragma unroll
    for (int im = 0; im < 4; im++) {
        const int r0 = bm + wm + im * 16 + gr;
#pragma unroll
        for (int in = 0; in < 4; in++) {
            const int col = bn + wn + in * 8 + 2 * tig;
            float2 v0 = make_float2(acc[im][in][0], acc[im][in][1]);
            float2 v1 = make_float2(acc[im][in][2], acc[im][in][3]);
            if (EPI == 2 || EPI == 3) {
                const float2 bb = *(const float2*)&bias[col];
                v0.x += bb.x; v0.y += bb.y;
                v1.x += bb.x; v1.y += bb.y;
            }
            if (EPI == 2) {
                v0.x = fmaxf(v0.x, 0.f); v0.y = fmaxf(v0.y, 0.f);
                v1.x = fmaxf(v1.x, 0.f); v1.y = fmaxf(v1.y, 0.f);
            }
            if (EPI == 1 || EPI == 3) {
                const float2 c0 = *(const float2*)&Cadd[(size_t)r0 * NC + col];
                const float2 c1 = *(const float2*)&Cadd[(size_t)(r0 + 8) * NC + col];
                v0.x += c0.x; v0.y += c0.y;
                v1.x += c1.x; v1.y += c1.y;
            }
            *(float2*)&C[(size_t)r0 * NC + col]       = v0;
            *(float2*)&C[(size_t)(r0 + 8) * NC + col] = v1;
        }
    }
}

__global__ __launch_bounds__(256) void k_proj_tc()
{ gemm_mma<Dd, DFF, 0>(g_h, g_Wt_qkv, nullptr, nullptr, g_proj); }

__global__ __launch_bounds__(256) void k_wo_tc()
{ gemm_mma<Dd, Dd, 1>(g_att, g_Wt_o, g_h, nullptr, g_hres); }

__global__ __launch_bounds__(256) void k_ffn1_tc(const float* __restrict__ b1)
{ gemm_mma<Dd, DFF, 2>(g_h2, g_Wt_1, nullptr, b1, g_ffn); }

__global__ __launch_bounds__(256) void k_ffn2_tc(const float* __restrict__ b2,
                                                 float* __restrict__ out)
{ gemm_mma<DFF, Dd, 3>(g_ffn, g_Wt_2, g_h2, b2, out); }

// ============================================================================
// Triangle attention v3 — x-tiled + double-buffered pipeline.
// Block = (x-tile of 8, h, b); 256 threads; 1 barrier per a-step.
// Prefetch (registers) for step a+1 overlaps compute of step a.
// ============================================================================
__global__ __launch_bounds__(256) void attn3_kernel(const unsigned char* __restrict__ mask)
{
    const int xt = blockIdx.x;
    const int hh = blockIdx.y;
    const int b  = blockIdx.z;
    const int t  = threadIdx.x;
    const int y  = t >> 2;
    const int dq = t & 3;
    const int x0 = xt * TX;

    __shared__ float rk_s[2][Nn][36];
    __shared__ float rv_s[2][Nn][36];
    __shared__ float lk_s[2][TX][36];
    __shared__ float lv_s[2][TX][36];

    // loader geometry: u in {t, t+256}; row = u>>3, c4 = (u&7)*4
    const int r0c = t >> 3;          // row for u = t           (0..31)
    const int r1c = r0c + 32;        // row for u = t+256       (32..63)
    const int c4  = (t & 7) * 4;
    const int xr  = t >> 3;          // lk/lv row (t<64)
    const int lc4 = (t & 7) * 4;

    float4 prk0, prk1, prv0, prv1, plk, plv;
    unsigned int pmn[TX], pmc[TX];

    const int mstride = Nn * Nn;

    // ---- prefetch a = 0 ----
    {
        const int baseR = ((b * Nn + 0) * Nn) * DFF + hh * DKk;
        prk0 = *(const float4*)&g_proj[baseR + r0c * DFF + 256 + c4];
        prv0 = *(const float4*)&g_proj[baseR + r0c * DFF + 768 + c4];
        prk1 = *(const float4*)&g_proj[baseR + r1c * DFF + 256 + c4];
        prv1 = *(const float4*)&g_proj[baseR + r1c * DFF + 768 + c4];
        if (t < 64) {
            const int baseL = ((b * Nn + x0 + xr) * Nn + 0) * DFF + hh * DKk;
            plk = *(const float4*)&g_proj[baseL + lc4];
            plv = *(const float4*)&g_proj[baseL + 512 + lc4];
        }
        const int mb = ((b * Nn + x0) * Nn + 0) * Nn + y;
#pragma unroll
        for (int xx = 0; xx < TX; xx++) pmn[xx] = mask[mb + xx * mstride];
    }
    // store into buffer 0
    *(float4*)&rk_s[0][r0c][c4] = prk0;
    *(float4*)&rv_s[0][r0c][c4] = prv0;
    *(float4*)&rk_s[0][r1c][c4] = prk1;
    *(float4*)&rv_s[0][r1c][c4] = prv1;
    if (t < 64) {
        *(float4*)&lk_s[0][xr][lc4] = plk;
        *(float4*)&lv_s[0][xr][lc4] = plv;
    }
    __syncthreads();

    float acc[TX][8];
    float m[TX], l[TX];
#pragma unroll
    for (int xx = 0; xx < TX; xx++) {
        m[xx] = -1e30f; l[xx] = 0.f;
#pragma unroll
        for (int j = 0; j < 8; j++) acc[xx][j] = 0.f;
    }

    const float qk_scale = 0.17677669529663687f;   // 1/sqrt(32)

    for (int a = 0; a < Nn; a++) {
        const int buf = a & 1;

        // rotate mask regs; prefetch step a+1 (overlaps compute below)
#pragma unroll
        for (int xx = 0; xx < TX; xx++) pmc[xx] = pmn[xx];
        if (a + 1 < Nn) {
            const int baseR = ((b * Nn + (a + 1)) * Nn) * DFF + hh * DKk;
            prk0 = *(const float4*)&g_proj[baseR + r0c * DFF + 256 + c4];
            prv0 = *(const float4*)&g_proj[baseR + r0c * DFF + 768 + c4];
            prk1 = *(const float4*)&g_proj[baseR + r1c * DFF + 256 + c4];
            prv1 = *(const float4*)&g_proj[baseR + r1c * DFF + 768 + c4];
            if (t < 64) {
                const int baseL = ((b * Nn + x0 + xr) * Nn + (a + 1)) * DFF + hh * DKk;
                plk = *(const float4*)&g_proj[baseL + lc4];
                plv = *(const float4*)&g_proj[baseL + 512 + lc4];
            }
            const int mb = ((b * Nn + x0) * Nn + (a + 1)) * Nn + y;
#pragma unroll
            for (int xx = 0; xx < TX; xx++) pmn[xx] = mask[mb + xx * mstride];
        }

        // ---- compute step a from buf ----
        const float4 rk0 = *(const float4*)&rk_s[buf][y][dq * 8];
        const float4 rk1 = *(const float4*)&rk_s[buf][y][dq * 8 + 4];
        const float4 rv0 = *(const float4*)&rv_s[buf][y][dq * 8];
        const float4 rv1 = *(const float4*)&rv_s[buf][y][dq * 8 + 4];

#pragma unroll
        for (int xx = 0; xx < TX; xx++) {
            const float4 lk0 = *(const float4*)&lk_s[buf][xx][dq * 8];
            const float4 lk1 = *(const float4*)&lk_s[buf][xx][dq * 8 + 4];
            float part = lk0.x * rk0.x + lk0.y * rk0.y + lk0.z * rk0.z + lk0.w * rk0.w
                       + lk1.x * rk1.x + lk1.y * rk1.y + lk1.z * rk1.z + lk1.w * rk1.w;
            part += __shfl_xor_sync(0xffffffffu, part, 1);
            part += __shfl_xor_sync(0xffffffffu, part, 2);
            float sc = part * qk_scale;
            if (pmc[xx]) sc = -1e9f;

            const float mn = fmaxf(m[xx], sc);
            const float cs = __expf(m[xx] - mn);
            const float p  = __expf(sc - mn);
            l[xx] = l[xx] * cs + p;
            m[xx] = mn;

            const float4 lv0 = *(const float4*)&lv_s[buf][xx][dq * 8];
            const float4 lv1 = *(const float4*)&lv_s[buf][xx][dq * 8 + 4];
            acc[xx][0] = acc[xx][0] * cs + p * lv0.x * rv0.x;
            acc[xx][1] = acc[xx][1] * cs + p * lv0.y * rv0.y;
            acc[xx][2] = acc[xx][2] * cs + p * lv0.z * rv0.z;
            acc[xx][3] = acc[xx][3] * cs + p * lv0.w * rv0.w;
            acc[xx][4] = acc[xx][4] * cs + p * lv1.x * rv1.x;
            acc[xx][5] = acc[xx][5] * cs + p * lv1.y * rv1.y;
            acc[xx][6] = acc[xx][6] * cs + p * lv1.z * rv1.z;
            acc[xx][7] = acc[xx][7] * cs + p * lv1.w * rv1.w;
        }

        // ---- store prefetched step a+1 into the other buffer ----
        if (a + 1 < Nn) {
            const int nb = buf ^ 1;
            *(float4*)&rk_s[nb][r0c][c4] = prk0;
            *(float4*)&rv_s[nb][r0c][c4] = prv0;
            *(float4*)&rk_s[nb][r1c][c4] = prk1;
            *(float4*)&rv_s[nb][r1c][c4] = prv1;
            if (t < 64) {
                *(float4*)&lk_s[nb][xr][lc4] = plk;
                *(float4*)&lv_s[nb][xr][lc4] = plv;
            }
            __syncthreads();
        }
    }

#pragma unroll
    for (int xx = 0; xx < TX; xx++) {
        const float inv = 1.0f / l[xx];
        const int ob = ((b * Nn + x0 + xx) * Nn + y) * Dd + hh * DKk + dq * 8;
        float4 v0, v1;
        v0.x = acc[xx][0] * inv; v0.y = acc[xx][1] * inv;
        v0.z = acc[xx][2] * inv; v0.w = acc[xx][3] * inv;
        v1.x = acc[xx][4] * inv; v1.y = acc[xx][5] * inv;
        v1.z = acc[xx][6] * inv; v1.w = acc[xx][7] * inv;
        *(float4*)&g_att[ob]     = v0;
        *(float4*)&g_att[ob + 4] = v1;
    }
}

// ============================================================================
// launch
// ============================================================================
extern "C" void kernel_launch(void* const* d_in, const int* in_sizes, int n_in,
                              void* d_out, int out_size)
{
    const float*         x    = (const float*)d_in[0];
    const unsigned char* mask = (const unsigned char*)d_in[1];
    const float*         Wlk  = (const float*)d_in[2];
    const float*         Wrk  = (const float*)d_in[3];
    const float*         Wlv  = (const float*)d_in[4];
    const float*         Wrv  = (const float*)d_in[5];
    const float*         Wo   = (const float*)d_in[6];
    const float*         W1   = (const float*)d_in[7];
    const float*         b1   = (const float*)d_in[8];
    const float*         W2   = (const float*)d_in[9];
    const float*         b2   = (const float*)d_in[10];
    const float*         g1   = (const float*)d_in[11];
    const float*         be1  = (const float*)d_in[12];
    const float*         g2   = (const float*)d_in[13];
    const float*         be2  = (const float*)d_in[14];
    float* out = (float*)d_out;

    k_tr_all<<<832, 256>>>(Wlk, Wrk, Wlv, Wrv, Wo, W1, W2);
    ln1_kernel<<<RR, 256>>>(x, g1, be1);
    k_proj_tc<<<dim3(DFF / 128, RR / 128), 256>>>();
    attn3_kernel<<<dim3(Nn / TX, Hh, Bb), 256>>>(mask);
    k_wo_tc<<<dim3(Dd / 128, RR / 128), 256>>>();
    ln2_kernel<<<RR, 256>>>(g2, be2);
    k_ffn1_tc<<<dim3(DFF / 128, RR / 128), 256>>>(b1);
    k_ffn2_tc<<<dim3(Dd / 128, RR / 128), 256>>>(b2, out);
}

// round 6
// speedup vs baseline: 2.5570x; 1.0316x over previous
#include <cuda_runtime.h>
#include <cstdint>

// ============================================================================
// EdgeTransformerLayer (B=2, N=64, D=256, H=8, DK=32, DFF=1024)
// GEMMs: mma.sync.m16n8k8 tf32 + ldmatrix + double-buffered SMEM pipeline.
// Attention: x-tiled, double-buffered, f32x2 packed math, no-max softmax.
// ============================================================================

namespace {
constexpr int Bb  = 2;
constexpr int Nn  = 64;
constexpr int Dd  = 256;
constexpr int Hh  = 8;
constexpr int DKk = 32;
constexpr int DFF = 1024;
constexpr int RR  = Bb * Nn * Nn;   // 8192
constexpr int SP  = 36;             // padded SMEM row stride (floats)
constexpr int TX  = 8;              // attention x-tile
constexpr int BUFW = 128 * SP;      // uint32 words per GEMM smem buffer
constexpr int DSMEM = 4 * BUFW * 4; // bytes: As[2] + Bs[2]
}

// ---- device-global scratch (no allocation allowed) --------------------------
__device__ float g_h     [RR * Dd];
__device__ float g_proj  [RR * DFF];   // cols: [0,256)=lk*scale [256,512)=rk [512,768)=lv [768,1024)=rv
__device__ float g_att   [RR * Dd];
__device__ float g_hres  [RR * Dd];
__device__ float g_h2    [RR * Dd];
__device__ float g_ffn   [RR * DFF];
__device__ float g_Wt_qkv[DFF * Dd];   // [1024,256], tf32-rounded
__device__ float g_Wt_o  [Dd * Dd];
__device__ float g_Wt_1  [DFF * Dd];
__device__ float g_Wt_2  [Dd * DFF];
__device__ unsigned char g_maskT[Bb * Nn * Nn * Nn];  // [b][a][y][x]

// ============================================================================
// helpers
// ============================================================================
__device__ __forceinline__ uint32_t smem_u32(const void* p) {
    uint32_t a;
    asm("{ .reg .u64 t; cvta.to.shared.u64 t, %1; cvt.u32.u64 %0, t; }" : "=r"(a) : "l"(p));
    return a;
}

__device__ __forceinline__ uint32_t f2tf32(float f) {
    uint32_t r;
    asm("cvt.rna.tf32.f32 %0, %1;" : "=r"(r) : "f"(f));
    return r;
}

__device__ __forceinline__ void mma_tf32(float c[4],
                                         uint32_t a0, uint32_t a1, uint32_t a2, uint32_t a3,
                                         uint32_t b0, uint32_t b1) {
    asm volatile(
        "mma.sync.aligned.m16n8k8.row.col.f32.tf32.tf32.f32 "
        "{%0,%1,%2,%3}, {%4,%5,%6,%7}, {%8,%9}, {%0,%1,%2,%3};"
        : "+f"(c[0]), "+f"(c[1]), "+f"(c[2]), "+f"(c[3])
        : "r"(a0), "r"(a1), "r"(a2), "r"(a3), "r"(b0), "r"(b1));
}

__device__ __forceinline__ void ldsm_x4(uint32_t r[4], uint32_t addr) {
    asm volatile("ldmatrix.sync.aligned.m8n8.x4.shared.b16 {%0,%1,%2,%3}, [%4];"
                 : "=r"(r[0]), "=r"(r[1]), "=r"(r[2]), "=r"(r[3]) : "r"(addr));
}
__device__ __forceinline__ void ldsm_x2(uint32_t r[2], uint32_t addr) {
    asm volatile("ldmatrix.sync.aligned.m8n8.x2.shared.b16 {%0,%1}, [%2];"
                 : "=r"(r[0]), "=r"(r[1]) : "r"(addr));
}

// ---- packed f32x2 ------------------------------------------------------------
typedef unsigned long long u64;
__device__ __forceinline__ u64 pk2(float lo, float hi) {
    u64 r; asm("mov.b64 %0, {%1,%2};" : "=l"(r) : "f"(lo), "f"(hi)); return r;
}
__device__ __forceinline__ void upk2(u64 v, float& lo, float& hi) {
    asm("mov.b64 {%0,%1}, %2;" : "=f"(lo), "=f"(hi) : "l"(v));
}
__device__ __forceinline__ u64 mul2(u64 a, u64 b) {
    u64 d; asm("mul.rn.f32x2 %0, %1, %2;" : "=l"(d) : "l"(a), "l"(b)); return d;
}
__device__ __forceinline__ u64 fma2(u64 a, u64 b, u64 c) {
    u64 d; asm("fma.rn.f32x2 %0, %1, %2, %3;" : "=l"(d) : "l"(a), "l"(b), "l"(c)); return d;
}

// ============================================================================
// prep kernel: weight transposes (tf32-rounded, Wlk pre-scaled) + mask transpose
// ids [0,832): weight tiles; ids [832,2880): mask bytes
// ============================================================================
__global__ __launch_bounds__(256) void k_prep(const float* __restrict__ Wlk,
                                              const float* __restrict__ Wrk,
                                              const float* __restrict__ Wlv,
                                              const float* __restrict__ Wrv,
                                              const float* __restrict__ Wo,
                                              const float* __restrict__ W1,
                                              const float* __restrict__ W2,
                                              const unsigned char* __restrict__ mask)
{
    const int id = blockIdx.x;
    if (id >= 832) {
        // mask transpose: out[b][a][y][x] = in[b][x][a][y]
        const int g = (id - 832) * 256 + threadIdx.x;
        const int x  = g & 63;
        const int yy = (g >> 6) & 63;
        const int a  = (g >> 12) & 63;
        const int bb = g >> 18;
        g_maskT[g] = mask[(((bb * 64 + x) * 64 + a) * 64) + yy];
        return;
    }

    __shared__ float tile[32][33];
    const float* src;
    float* dst;
    float scale = 1.0f;
    int K, N, n0, k0;
    if (id < 320) {
        const int w = id >> 6;
        const int tl = id & 63;
        src = (w == 0) ? Wlk : (w == 1) ? Wrk : (w == 2) ? Wlv : (w == 3) ? Wrv : Wo;
        dst = (w < 4) ? (g_Wt_qkv + w * 256 * 256) : g_Wt_o;
        if (w == 0) scale = 0.17677669529663687f;   // 1/sqrt(32) folded into Wlk
        K = 256; N = 256;
        n0 = (tl & 7) * 32; k0 = (tl >> 3) * 32;
    } else if (id < 576) {
        const int tl = id - 320;
        src = W1; dst = g_Wt_1; K = 256; N = 1024;
        n0 = (tl & 31) * 32; k0 = (tl >> 5) * 32;
    } else {
        const int tl = id - 576;
        src = W2; dst = g_Wt_2; K = 1024; N = 256;
        n0 = (tl & 7) * 32; k0 = (tl >> 3) * 32;
    }
    const int tx = threadIdx.x & 31;
    const int ty = threadIdx.x >> 5;
#pragma unroll
    for (int r = ty; r < 32; r += 8)
        tile[r][tx] = src[(size_t)(k0 + r) * N + n0 + tx];
    __syncthreads();
#pragma unroll
    for (int r = ty; r < 32; r += 8)
        dst[(size_t)(n0 + r) * K + k0 + tx] = __uint_as_float(f2tf32(tile[tx][r] * scale));
}

// ============================================================================
// LayerNorm
// ============================================================================
__device__ __forceinline__ void ln_body(const float* __restrict__ in,
                                        const float* __restrict__ gam,
                                        const float* __restrict__ bet,
                                        float* __restrict__ out)
{
    const int row = blockIdx.x;
    const int t   = threadIdx.x;
    const float v = in[row * Dd + t];
    float s = v, s2 = v * v;
#pragma unroll
    for (int o = 16; o; o >>= 1) {
        s  += __shfl_xor_sync(0xffffffffu, s,  o);
        s2 += __shfl_xor_sync(0xffffffffu, s2, o);
    }
    __shared__ float ws[8], ws2[8];
    if ((t & 31) == 0) { ws[t >> 5] = s; ws2[t >> 5] = s2; }
    __syncthreads();
    float ts = 0.f, ts2 = 0.f;
#pragma unroll
    for (int i = 0; i < 8; i++) { ts += ws[i]; ts2 += ws2[i]; }
    const float mean = ts * (1.0f / Dd);
    const float var  = ts2 * (1.0f / Dd) - mean * mean;
    const float inv  = rsqrtf(var + 1e-5f);
    out[row * Dd + t] = (v - mean) * inv * gam[t] + bet[t];
}

__global__ __launch_bounds__(256) void ln1_kernel(const float* __restrict__ x,
                                                  const float* __restrict__ g1,
                                                  const float* __restrict__ be1)
{ ln_body(x, g1, be1, g_h); }

__global__ __launch_bounds__(256) void ln2_kernel(const float* __restrict__ g2,
                                                  const float* __restrict__ be2)
{ ln_body(g_hres, g2, be2, g_h2); }

// ============================================================================
// tf32 mma GEMM, double-buffered SMEM (dynamic): one barrier per K-chunk.
// C[M,NC] = A[M,K] @ Wt^T, Wt [NC,K] pre-rounded tf32 (no cvt on B path).
// CTA 128x128, 8 warps, warp tile 64x32, K chunks of 32.
// ============================================================================
template <int K, int NC, int EPI>
__device__ __forceinline__ void gemm_mma(const float* __restrict__ A,
                                         const float* __restrict__ Wt,
                                         const float* __restrict__ Cadd,
                                         const float* __restrict__ bias,
                                         float* __restrict__ C)
{
    constexpr int NCH = K / 32;
    extern __shared__ uint32_t dsm[];
    uint32_t* As = dsm;              // [2][BUFW]
    uint32_t* Bs = dsm + 2 * BUFW;   // [2][BUFW]
    constexpr uint32_t BUFBYTES = BUFW * 4;

    const int t    = threadIdx.x;
    const int lane = t & 31;
    const int wid  = t >> 5;
    const int gr   = lane >> 2;
    const int tig  = lane & 3;
    const int wm   = (wid & 1) * 64;
    const int wn   = (wid >> 1) * 32;

    const int bm = blockIdx.y * 128;
    const int bn = blockIdx.x * 128;

    const uint32_t a_base = smem_u32(As) + ((wm + (lane & 15)) * SP + ((lane >> 4) & 1) * 4) * 4;
    const uint32_t b_base = smem_u32(Bs) + ((wn + (lane & 7)) * SP + ((lane >> 3) & 1) * 4) * 4;

    const int lrow  = t >> 1;
    const int lkoff = (t & 1) * 16;
    const float4* Ag = (const float4*)(A  + (size_t)(bm + lrow) * K + lkoff);
    const float4* Bg = (const float4*)(Wt + (size_t)(bn + lrow) * K + lkoff);

    float4 pa[4], pb[4];
#pragma unroll
    for (int i = 0; i < 4; i++) { pa[i] = Ag[i]; pb[i] = Bg[i]; }

    float acc[4][4][4];
#pragma unroll
    for (int im = 0; im < 4; im++)
#pragma unroll
        for (int in = 0; in < 4; in++)
#pragma unroll
            for (int j = 0; j < 4; j++) acc[im][in][j] = 0.f;

    uint32_t* asw = As + lrow * SP + lkoff;
    uint32_t* bsw = Bs + lrow * SP + lkoff;

    // stage chunk 0 into buffer 0
#pragma unroll
    for (int i = 0; i < 4; i++) {
        uint4 ua;
        ua.x = f2tf32(pa[i].x); ua.y = f2tf32(pa[i].y);
        ua.z = f2tf32(pa[i].z); ua.w = f2tf32(pa[i].w);
        *(uint4*)(asw + i * 4) = ua;
        *(uint4*)(bsw + i * 4) = *(const uint4*)&pb[i];   // weights pre-rounded
    }
    __syncthreads();

    for (int c = 0; c < NCH; c++) {
        const int buf = c & 1;

        if (c + 1 < NCH) {                     // prefetch next chunk (LDG)
#pragma unroll
            for (int i = 0; i < 4; i++) {
                pa[i] = Ag[(c + 1) * 8 + i];
                pb[i] = Bg[(c + 1) * 8 + i];
            }
        }

        // compute chunk c from buf
        const uint32_t a_addr = a_base + buf * BUFBYTES;
        const uint32_t b_addr = b_base + buf * BUFBYTES;
#pragma unroll
        for (int ks = 0; ks < 4; ks++) {
            uint32_t af[4][4], bf[4][2];
#pragma unroll
            for (int im = 0; im < 4; im++)
                ldsm_x4(af[im], a_addr + (uint32_t)(im * 16 * SP * 4 + ks * 32));
#pragma unroll
            for (int in = 0; in < 4; in++)
                ldsm_x2(bf[in], b_addr + (uint32_t)(in * 8 * SP * 4 + ks * 32));
#pragma unroll
            for (int im = 0; im < 4; im++)
#pragma unroll
                for (int in = 0; in < 4; in++)
                    mma_tf32(acc[im][in], af[im][0], af[im][1], af[im][2], af[im][3],
                             bf[in][0], bf[in][1]);
        }

        // stage chunk c+1 into the other buffer (overlaps with MMA latency)
        if (c + 1 < NCH) {
            const int ofs = (buf ^ 1) * BUFW;
#pragma unroll
            for (int i = 0; i < 4; i++) {
                uint4 ua;
                ua.x = f2tf32(pa[i].x); ua.y = f2tf32(pa[i].y);
                ua.z = f2tf32(pa[i].z); ua.w = f2tf32(pa[i].w);
                *(uint4*)(asw + ofs + i * 4) = ua;
                *(uint4*)(bsw + ofs + i * 4) = *(const uint4*)&pb[i];
            }
            __syncthreads();
        }
    }

    // epilogue
#pragma unroll
    for (int im = 0; im < 4; im++) {
        const int r0 = bm + wm + im * 16 + gr;
#pragma unroll
        for (int in = 0; in < 4; in++) {
            const int col = bn + wn + in * 8 + 2 * tig;
            float2 v0 = make_float2(acc[im][in][0], acc[im][in][1]);
            float2 v1 = make_float2(acc[im][in][2], acc[im][in][3]);
            if (EPI == 2 || EPI == 3) {
                const float2 bb = *(const float2*)&bias[col];
                v0.x += bb.x; v0.y += bb.y;
                v1.x += bb.x; v1.y += bb.y;
            }
            if (EPI == 2) {
                v0.x = fmaxf(v0.x, 0.f); v0.y = fmaxf(v0.y, 0.f);
                v1.x = fmaxf(v1.x, 0.f); v1.y = fmaxf(v1.y, 0.f);
            }
            if (EPI == 1 || EPI == 3) {
                const float2 c0 = *(const float2*)&Cadd[(size_t)r0 * NC + col];
                const float2 c1 = *(const float2*)&Cadd[(size_t)(r0 + 8) * NC + col];
                v0.x += c0.x; v0.y += c0.y;
                v1.x += c1.x; v1.y += c1.y;
            }
            *(float2*)&C[(size_t)r0 * NC + col]       = v0;
            *(float2*)&C[(size_t)(r0 + 8) * NC + col] = v1;
        }
    }
}

__global__ __launch_bounds__(256) void k_proj_tc()
{ gemm_mma<Dd, DFF, 0>(g_h, g_Wt_qkv, nullptr, nullptr, g_proj); }

__global__ __launch_bounds__(256) void k_wo_tc()
{ gemm_mma<Dd, Dd, 1>(g_att, g_Wt_o, g_h, nullptr, g_hres); }

__global__ __launch_bounds__(256) void k_ffn1_tc(const float* __restrict__ b1)
{ gemm_mma<Dd, DFF, 2>(g_h2, g_Wt_1, nullptr, b1, g_ffn); }

__global__ __launch_bounds__(256) void k_ffn2_tc(const float* __restrict__ b2,
                                                 float* __restrict__ out)
{ gemm_mma<DFF, Dd, 3>(g_ffn, g_Wt_2, g_h2, b2, out); }

// ============================================================================
// Triangle attention v4 — x-tiled, double-buffered, f32x2, no-max softmax.
// Block = (x-tile of 8, h, b); 256 threads; thread owns (y = t>>2, dq = t&3).
// lk columns of g_proj are pre-scaled by 1/sqrt(DK).
// ============================================================================
__global__ __launch_bounds__(256) void attn4_kernel()
{
    const int xt = blockIdx.x;
    const int hh = blockIdx.y;
    const int b  = blockIdx.z;
    const int t  = threadIdx.x;
    const int y  = t >> 2;
    const int dq = t & 3;
    const int x0 = xt * TX;

    __shared__ float rk_s[2][Nn][36];
    __shared__ float rv_s[2][Nn][36];
    __shared__ float lk_s[2][TX][36];
    __shared__ float lv_s[2][TX][36];

    const int r0c = t >> 3;
    const int r1c = r0c + 32;
    const int c4  = (t & 7) * 4;
    const int xr  = t >> 3;
    const int lc4 = (t & 7) * 4;

    float4 prk0, prk1, prv0, prv1, plk, plv;
    u64 pmN, pmC;

    // ---- prefetch a = 0 ----
    {
        const int baseR = ((b * Nn + 0) * Nn) * DFF + hh * DKk;
        prk0 = *(const float4*)&g_proj[baseR + r0c * DFF + 256 + c4];
        prv0 = *(const float4*)&g_proj[baseR + r0c * DFF + 768 + c4];
        prk1 = *(const float4*)&g_proj[baseR + r1c * DFF + 256 + c4];
        prv1 = *(const float4*)&g_proj[baseR + r1c * DFF + 768 + c4];
        if (t < 64) {
            const int baseL = ((b * Nn + x0 + xr) * Nn + 0) * DFF + hh * DKk;
            plk = *(const float4*)&g_proj[baseL + lc4];
            plv = *(const float4*)&g_proj[baseL + 512 + lc4];
        }
        pmN = *(const u64*)&g_maskT[(((b * Nn + 0) * Nn + y) << 6) + x0];
    }
    *(float4*)&rk_s[0][r0c][c4] = prk0;
    *(float4*)&rv_s[0][r0c][c4] = prv0;
    *(float4*)&rk_s[0][r1c][c4] = prk1;
    *(float4*)&rv_s[0][r1c][c4] = prv1;
    if (t < 64) {
        *(float4*)&lk_s[0][xr][lc4] = plk;
        *(float4*)&lv_s[0][xr][lc4] = plv;
    }
    __syncthreads();

    u64 acc[TX][4];
    float l[TX];
#pragma unroll
    for (int xx = 0; xx < TX; xx++) {
        l[xx] = 0.f;
#pragma unroll
        for (int j = 0; j < 4; j++) acc[xx][j] = 0ull;
    }

    for (int a = 0; a < Nn; a++) {
        const int buf = a & 1;

        pmC = pmN;
        if (a + 1 < Nn) {   // prefetch a+1 (overlaps compute)
            const int baseR = ((b * Nn + (a + 1)) * Nn) * DFF + hh * DKk;
            prk0 = *(const float4*)&g_proj[baseR + r0c * DFF + 256 + c4];
            prv0 = *(const float4*)&g_proj[baseR + r0c * DFF + 768 + c4];
            prk1 = *(const float4*)&g_proj[baseR + r1c * DFF + 256 + c4];
            prv1 = *(const float4*)&g_proj[baseR + r1c * DFF + 768 + c4];
            if (t < 64) {
                const int baseL = ((b * Nn + x0 + xr) * Nn + (a + 1)) * DFF + hh * DKk;
                plk = *(const float4*)&g_proj[baseL + lc4];
                plv = *(const float4*)&g_proj[baseL + 512 + lc4];
            }
            pmN = *(const u64*)&g_maskT[(((b * Nn + (a + 1)) * Nn + y) << 6) + x0];
        }

        // ---- compute step a ----
        const ulonglong2 rka = *(const ulonglong2*)&rk_s[buf][y][dq * 8];
        const ulonglong2 rkb = *(const ulonglong2*)&rk_s[buf][y][dq * 8 + 4];
        const ulonglong2 rva = *(const ulonglong2*)&rv_s[buf][y][dq * 8];
        const ulonglong2 rvb = *(const ulonglong2*)&rv_s[buf][y][dq * 8 + 4];

#pragma unroll
        for (int xx = 0; xx < TX; xx++) {
            const ulonglong2 lka = *(const ulonglong2*)&lk_s[buf][xx][dq * 8];
            const ulonglong2 lkb = *(const ulonglong2*)&lk_s[buf][xx][dq * 8 + 4];
            u64 s2 = mul2(lka.x, rka.x);
            s2 = fma2(lka.y, rka.y, s2);
            s2 = fma2(lkb.x, rkb.x, s2);
            s2 = fma2(lkb.y, rkb.y, s2);
            float lo, hi;
            upk2(s2, lo, hi);
            float part = lo + hi;
            part += __shfl_xor_sync(0xffffffffu, part, 1);
            part += __shfl_xor_sync(0xffffffffu, part, 2);
            const float sc = ((pmC >> (xx * 8)) & 0xffull) ? -1e9f : part;
            const float p  = __expf(sc);      // |sc| bounded; masked underflows to 0
            l[xx] += p;
            const u64 pp = pk2(p, p);
            const ulonglong2 lva = *(const ulonglong2*)&lv_s[buf][xx][dq * 8];
            const ulonglong2 lvb = *(const ulonglong2*)&lv_s[buf][xx][dq * 8 + 4];
            acc[xx][0] = fma2(mul2(lva.x, rva.x), pp, acc[xx][0]);
            acc[xx][1] = fma2(mul2(lva.y, rva.y), pp, acc[xx][1]);
            acc[xx][2] = fma2(mul2(lvb.x, rvb.x), pp, acc[xx][2]);
            acc[xx][3] = fma2(mul2(lvb.y, rvb.y), pp, acc[xx][3]);
        }

        // ---- store prefetched a+1 into the other buffer ----
        if (a + 1 < Nn) {
            const int nb = buf ^ 1;
            *(float4*)&rk_s[nb][r0c][c4] = prk0;
            *(float4*)&rv_s[nb][r0c][c4] = prv0;
            *(float4*)&rk_s[nb][r1c][c4] = prk1;
            *(float4*)&rv_s[nb][r1c][c4] = prv1;
            if (t < 64) {
                *(float4*)&lk_s[nb][xr][lc4] = plk;
                *(float4*)&lv_s[nb][xr][lc4] = plv;
            }
            __syncthreads();
        }
    }

#pragma unroll
    for (int xx = 0; xx < TX; xx++) {
        const float inv = 1.0f / l[xx];
        const int ob = ((b * Nn + x0 + xx) * Nn + y) * Dd + hh * DKk + dq * 8;
        float a0, a1, a2, a3, a4, a5, a6, a7;
        upk2(acc[xx][0], a0, a1);
        upk2(acc[xx][1], a2, a3);
        upk2(acc[xx][2], a4, a5);
        upk2(acc[xx][3], a6, a7);
        float4 v0, v1;
        v0.x = a0 * inv; v0.y = a1 * inv; v0.z = a2 * inv; v0.w = a3 * inv;
        v1.x = a4 * inv; v1.y = a5 * inv; v1.z = a6 * inv; v1.w = a7 * inv;
        *(float4*)&g_att[ob]     = v0;
        *(float4*)&g_att[ob + 4] = v1;
    }
}

// ============================================================================
// launch
// ============================================================================
extern "C" void kernel_launch(void* const* d_in, const int* in_sizes, int n_in,
                              void* d_out, int out_size)
{
    const float*         x    = (const float*)d_in[0];
    const unsigned char* mask = (const unsigned char*)d_in[1];
    const float*         Wlk  = (const float*)d_in[2];
    const float*         Wrk  = (const float*)d_in[3];
    const float*         Wlv  = (const float*)d_in[4];
    const float*         Wrv  = (const float*)d_in[5];
    const float*         Wo   = (const float*)d_in[6];
    const float*         W1   = (const float*)d_in[7];
    const float*         b1   = (const float*)d_in[8];
    const float*         W2   = (const float*)d_in[9];
    const float*         b2   = (const float*)d_in[10];
    const float*         g1   = (const float*)d_in[11];
    const float*         be1  = (const float*)d_in[12];
    const float*         g2   = (const float*)d_in[13];
    const float*         be2  = (const float*)d_in[14];
    float* out = (float*)d_out;

    // allow >48KB dynamic smem on the GEMM kernels (idempotent, not captured)
    cudaFuncSetAttribute(k_proj_tc, cudaFuncAttributeMaxDynamicSharedMemorySize, DSMEM);
    cudaFuncSetAttribute(k_wo_tc,   cudaFuncAttributeMaxDynamicSharedMemorySize, DSMEM);
    cudaFuncSetAttribute(k_ffn1_tc, cudaFuncAttributeMaxDynamicSharedMemorySize, DSMEM);
    cudaFuncSetAttribute(k_ffn2_tc, cudaFuncAttributeMaxDynamicSharedMemorySize, DSMEM);

    k_prep<<<2880, 256>>>(Wlk, Wrk, Wlv, Wrv, Wo, W1, W2, mask);
    ln1_kernel<<<RR, 256>>>(x, g1, be1);
    k_proj_tc<<<dim3(DFF / 128, RR / 128), 256, DSMEM>>>();
    attn4_kernel<<<dim3(Nn / TX, Hh, Bb), 256>>>();
    k_wo_tc<<<dim3(Dd / 128, RR / 128), 256, DSMEM>>>();
    ln2_kernel<<<RR, 256>>>(g2, be2);
    k_ffn1_tc<<<dim3(DFF / 128, RR / 128), 256, DSMEM>>>(b1);
    k_ffn2_tc<<<dim3(Dd / 128, RR / 128), 256, DSMEM>>>(b2, out);
}

// round 8
// speedup vs baseline: 3.2214x; 1.2598x over previous
#include <cuda_runtime.h>
#include <cuda_fp16.h>
#include <cstdint>

// ============================================================================
// EdgeTransformerLayer (B=2, N=64, D=256, H=8, DK=32, DFF=1024)
// GEMMs: mma.sync.m16n8k16 fp16 (fp32 accum) + ldmatrix, double-buffered SMEM.
// Attention: x-split across warp halves (512 thr), double-buffered, f32x2.
// ============================================================================

namespace {
constexpr int Bb  = 2;
constexpr int Nn  = 64;
constexpr int Dd  = 256;
constexpr int Hh  = 8;
constexpr int DKk = 32;
constexpr int DFF = 1024;
constexpr int RR  = Bb * Nn * Nn;   // 8192
constexpr int SPH = 40;             // GEMM smem row stride (halfs): 80B
constexpr int BUFH = 128 * SPH;     // halfs per GEMM smem buffer
}

// ---- device-global scratch (no allocation allowed) --------------------------
__device__ float  g_h     [RR * Dd];
__device__ float  g_proj  [RR * DFF];  // [0,256)=lk*scale [256,512)=rk [512,768)=lv [768,1024)=rv
__device__ float  g_att   [RR * Dd];
__device__ float  g_hres  [RR * Dd];
__device__ float  g_h2    [RR * Dd];
__device__ float  g_ffn   [RR * DFF];
__device__ __half g_Wh_qkv[DFF * Dd];  // [1024,256] fp16, Wlk pre-scaled
__device__ __half g_Wh_o  [Dd * Dd];
__device__ __half g_Wh_1  [DFF * Dd];
__device__ __half g_Wh_2  [Dd * DFF];
__device__ unsigned char g_maskT[Bb * Nn * Nn * Nn];  // [b][a][y][x]

// ============================================================================
// helpers
// ============================================================================
__device__ __forceinline__ uint32_t smem_u32(const void* p) {
    uint32_t a;
    asm("{ .reg .u64 t; cvta.to.shared.u64 t, %1; cvt.u32.u64 %0, t; }" : "=r"(a) : "l"(p));
    return a;
}

__device__ __forceinline__ void mma_f16(float c[4],
                                        uint32_t a0, uint32_t a1, uint32_t a2, uint32_t a3,
                                        uint32_t b0, uint32_t b1) {
    asm volatile(
        "mma.sync.aligned.m16n8k16.row.col.f32.f16.f16.f32 "
        "{%0,%1,%2,%3}, {%4,%5,%6,%7}, {%8,%9}, {%0,%1,%2,%3};"
        : "+f"(c[0]), "+f"(c[1]), "+f"(c[2]), "+f"(c[3])
        : "r"(a0), "r"(a1), "r"(a2), "r"(a3), "r"(b0), "r"(b1));
}

__device__ __forceinline__ void ldsm_x4(uint32_t r[4], uint32_t addr) {
    asm volatile("ldmatrix.sync.aligned.m8n8.x4.shared.b16 {%0,%1,%2,%3}, [%4];"
                 : "=r"(r[0]), "=r"(r[1]), "=r"(r[2]), "=r"(r[3]) : "r"(addr));
}
__device__ __forceinline__ void ldsm_x2(uint32_t r[2], uint32_t addr) {
    asm volatile("ldmatrix.sync.aligned.m8n8.x2.shared.b16 {%0,%1}, [%2];"
                 : "=r"(r[0]), "=r"(r[1]) : "r"(addr));
}

__device__ __forceinline__ uint32_t h2u(__half2 h) {
    uint32_t u; asm("mov.b32 %0, %1;" : "=r"(u) : "r"(*(uint32_t*)&h)); return u;
}

// ---- packed f32x2 ------------------------------------------------------------
typedef unsigned long long u64;
__device__ __forceinline__ u64 pk2(float lo, float hi) {
    u64 r; asm("mov.b64 %0, {%1,%2};" : "=l"(r) : "f"(lo), "f"(hi)); return r;
}
__device__ __forceinline__ void upk2(u64 v, float& lo, float& hi) {
    asm("mov.b64 {%0,%1}, %2;" : "=f"(lo), "=f"(hi) : "l"(v));
}
__device__ __forceinline__ u64 mul2(u64 a, u64 b) {
    u64 d; asm("mul.rn.f32x2 %0, %1, %2;" : "=l"(d) : "l"(a), "l"(b)); return d;
}
__device__ __forceinline__ u64 fma2(u64 a, u64 b, u64 c) {
    u64 d; asm("fma.rn.f32x2 %0, %1, %2, %3;" : "=l"(d) : "l"(a), "l"(b), "l"(c)); return d;
}

// ============================================================================
// prep: weight transpose -> [N,K] fp16 (Wlk pre-scaled) + mask transpose
// ============================================================================
__device__ __forceinline__ __half* trh_dst(int which) {
    switch (which) {
        case 0: return g_Wh_qkv;
        case 1: return g_Wh_qkv + 256 * 256;
        case 2: return g_Wh_qkv + 512 * 256;
        case 3: return g_Wh_qkv + 768 * 256;
        case 4: return g_Wh_o;
        case 5: return g_Wh_1;
        default: return g_Wh_2;
    }
}

__global__ __launch_bounds__(256) void k_prep(const float* __restrict__ Wlk,
                                              const float* __restrict__ Wrk,
                                              const float* __restrict__ Wlv,
                                              const float* __restrict__ Wrv,
                                              const float* __restrict__ Wo,
                                              const float* __restrict__ W1,
                                              const float* __restrict__ W2,
                                              const unsigned char* __restrict__ mask)
{
    const int id = blockIdx.x;
    if (id >= 832) {
        const int g = (id - 832) * 256 + threadIdx.x;
        const int x  = g & 63;
        const int yy = (g >> 6) & 63;
        const int a  = (g >> 12) & 63;
        const int bb = g >> 18;
        g_maskT[g] = mask[(((bb * 64 + x) * 64 + a) * 64) + yy];
        return;
    }

    __shared__ float tile[32][33];
    const float* src;
    __half* dst;
    float scale = 1.0f;
    int K, N, n0, k0;
    if (id < 320) {
        const int w = id >> 6;
        const int tl = id & 63;
        src = (w == 0) ? Wlk : (w == 1) ? Wrk : (w == 2) ? Wlv : (w == 3) ? Wrv : Wo;
        dst = trh_dst(w);
        if (w == 0) scale = 0.17677669529663687f;   // 1/sqrt(32)
        K = 256; N = 256;
        n0 = (tl & 7) * 32; k0 = (tl >> 3) * 32;
    } else if (id < 576) {
        const int tl = id - 320;
        src = W1; dst = g_Wh_1; K = 256; N = 1024;
        n0 = (tl & 31) * 32; k0 = (tl >> 5) * 32;
    } else {
        const int tl = id - 576;
        src = W2; dst = g_Wh_2; K = 1024; N = 256;
        n0 = (tl & 7) * 32; k0 = (tl >> 3) * 32;
    }
    const int tx = threadIdx.x & 31;
    const int ty = threadIdx.x >> 5;
#pragma unroll
    for (int r = ty; r < 32; r += 8)
        tile[r][tx] = src[(size_t)(k0 + r) * N + n0 + tx];
    __syncthreads();
#pragma unroll
    for (int r = ty; r < 32; r += 8)
        dst[(size_t)(n0 + r) * K + k0 + tx] = __float2half_rn(tile[tx][r] * scale);
}

// ============================================================================
// LayerNorm: warp per row (8 rows / 256-thread block)
// ============================================================================
__device__ __forceinline__ void ln_body(const float* __restrict__ in,
                                        const float* __restrict__ gam,
                                        const float* __restrict__ bet,
                                        float* __restrict__ out)
{
    const int row  = blockIdx.x * 8 + (threadIdx.x >> 5);
    const int lane = threadIdx.x & 31;
    const float* rp = in + (size_t)row * Dd + lane * 8;
    const float4 v0 = *(const float4*)rp;
    const float4 v1 = *(const float4*)(rp + 4);
    float s  = v0.x + v0.y + v0.z + v0.w + v1.x + v1.y + v1.z + v1.w;
    float s2 = v0.x*v0.x + v0.y*v0.y + v0.z*v0.z + v0.w*v0.w
             + v1.x*v1.x + v1.y*v1.y + v1.z*v1.z + v1.w*v1.w;
#pragma unroll
    for (int o = 16; o; o >>= 1) {
        s  += __shfl_xor_sync(0xffffffffu, s,  o);
        s2 += __shfl_xor_sync(0xffffffffu, s2, o);
    }
    const float mean = s * (1.0f / Dd);
    const float var  = s2 * (1.0f / Dd) - mean * mean;
    const float inv  = rsqrtf(var + 1e-5f);
    const float4 g0 = *(const float4*)(gam + lane * 8);
    const float4 g1 = *(const float4*)(gam + lane * 8 + 4);
    const float4 b0 = *(const float4*)(bet + lane * 8);
    const float4 b1 = *(const float4*)(bet + lane * 8 + 4);
    float4 o0, o1;
    o0.x = (v0.x - mean) * inv * g0.x + b0.x;
    o0.y = (v0.y - mean) * inv * g0.y + b0.y;
    o0.z = (v0.z - mean) * inv * g0.z + b0.z;
    o0.w = (v0.w - mean) * inv * g0.w + b0.w;
    o1.x = (v1.x - mean) * inv * g1.x + b1.x;
    o1.y = (v1.y - mean) * inv * g1.y + b1.y;
    o1.z = (v1.z - mean) * inv * g1.z + b1.z;
    o1.w = (v1.w - mean) * inv * g1.w + b1.w;
    float* op = out + (size_t)row * Dd + lane * 8;
    *(float4*)op       = o0;
    *(float4*)(op + 4) = o1;
}

__global__ __launch_bounds__(256) void ln1_kernel(const float* __restrict__ x,
                                                  const float* __restrict__ g1,
                                                  const float* __restrict__ be1)
{ ln_body(x, g1, be1, g_h); }

__global__ __launch_bounds__(256) void ln2_kernel(const float* __restrict__ g2,
                                                  const float* __restrict__ be2)
{ ln_body(g_hres, g2, be2, g_h2); }

// ============================================================================
// fp16 mma GEMM: C[M,NC] = A[M,K] @ Wh^T, Wh [NC,K] fp16 row-major.
// CTA 128x128, 8 warps (2x4), warp tile 64x32. K chunks of 32 (2 k16 steps).
// Double-buffered SMEM. EPI: 0 none; 1 +Cadd; 2 +bias,relu; 3 +bias,+Cadd.
// ============================================================================
template <int K, int NC, int EPI>
__device__ __forceinline__ void gemm_mma(const float* __restrict__ A,
                                         const __half* __restrict__ Wh,
                                         const float* __restrict__ Cadd,
                                         const float* __restrict__ bias,
                                         float* __restrict__ C)
{
    constexpr int NCH = K / 32;
    __shared__ __half As[2][BUFH];
    __shared__ __half Bs[2][BUFH];
    constexpr uint32_t BUFBYTES = BUFH * 2;

    const int t    = threadIdx.x;
    const int lane = t & 31;
    const int wid  = t >> 5;
    const int gr   = lane >> 2;
    const int tig  = lane & 3;
    const int wm   = (wid & 1) * 64;
    const int wn   = (wid >> 1) * 32;

    const int bm = blockIdx.y * 128;
    const int bn = blockIdx.x * 128;

    const uint32_t a_base = smem_u32(As) +
        ((wm + (lane & 15)) * SPH + ((lane >> 4) & 1) * 8) * 2;
    const uint32_t b_base = smem_u32(Bs) +
        ((wn + (lane & 7)) * SPH + ((lane >> 3) & 1) * 8) * 2;

    // staging: row = t>>1, 16 elements at half-offset (t&1)*16
    const int lrow = t >> 1;
    const int lko  = (t & 1) * 16;
    const float4* Ag  = (const float4*)(A + (size_t)(bm + lrow) * K + lko);
    const uint4*  Bgh = (const uint4*)(Wh + (size_t)(bn + lrow) * K);
    const int     bgi = (t & 1) * 2;     // uint4 index base; + c*4 per chunk

    float4 pa[4];
    uint4  pb0, pb1;                     // 16 halfs = 2 uint4 (FIX: was 1)
#pragma unroll
    for (int i = 0; i < 4; i++) pa[i] = Ag[i];
    pb0 = Bgh[bgi];
    pb1 = Bgh[bgi + 1];

    float acc[4][4][4];
#pragma unroll
    for (int im = 0; im < 4; im++)
#pragma unroll
        for (int in = 0; in < 4; in++)
#pragma unroll
            for (int j = 0; j < 4; j++) acc[im][in][j] = 0.f;

    // stage chunk 0 into buffer 0
    {
        uint32_t q[8];
#pragma unroll
        for (int i = 0; i < 4; i++) {
            q[2*i]   = h2u(__floats2half2_rn(pa[i].x, pa[i].y));
            q[2*i+1] = h2u(__floats2half2_rn(pa[i].z, pa[i].w));
        }
        __half* asw = &As[0][lrow * SPH + lko];
        *(uint4*)asw       = make_uint4(q[0], q[1], q[2], q[3]);
        *(uint4*)(asw + 8) = make_uint4(q[4], q[5], q[6], q[7]);
        __half* bsw = &Bs[0][lrow * SPH + lko];
        *(uint4*)bsw       = pb0;
        *(uint4*)(bsw + 8) = pb1;
    }
    __syncthreads();

    for (int c = 0; c < NCH; c++) {
        const int buf = c & 1;

        if (c + 1 < NCH) {                 // prefetch next chunk
#pragma unroll
            for (int i = 0; i < 4; i++) pa[i] = Ag[(c + 1) * 8 + i];
            pb0 = Bgh[bgi + (c + 1) * 4];
            pb1 = Bgh[bgi + (c + 1) * 4 + 1];
        }

        const uint32_t a_addr = a_base + buf * BUFBYTES;
        const uint32_t b_addr = b_base + buf * BUFBYTES;
#pragma unroll
        for (int ks = 0; ks < 2; ks++) {
            uint32_t af[4][4], bf[4][2];
#pragma unroll
            for (int im = 0; im < 4; im++)
                ldsm_x4(af[im], a_addr + (uint32_t)(im * 16 * SPH * 2 + ks * 32));
#pragma unroll
            for (int in = 0; in < 4; in++)
                ldsm_x2(bf[in], b_addr + (uint32_t)(in * 8 * SPH * 2 + ks * 32));
#pragma unroll
            for (int im = 0; im < 4; im++)
#pragma unroll
                for (int in = 0; in < 4; in++)
                    mma_f16(acc[im][in], af[im][0], af[im][1], af[im][2], af[im][3],
                            bf[in][0], bf[in][1]);
        }

        if (c + 1 < NCH) {                 // stage chunk c+1 into other buffer
            const int nb = buf ^ 1;
            uint32_t q[8];
#pragma unroll
            for (int i = 0; i < 4; i++) {
                q[2*i]   = h2u(__floats2half2_rn(pa[i].x, pa[i].y));
                q[2*i+1] = h2u(__floats2half2_rn(pa[i].z, pa[i].w));
            }
            __half* asw = &As[nb][lrow * SPH + lko];
            *(uint4*)asw       = make_uint4(q[0], q[1], q[2], q[3]);
            *(uint4*)(asw + 8) = make_uint4(q[4], q[5], q[6], q[7]);
            __half* bsw = &Bs[nb][lrow * SPH + lko];
            *(uint4*)bsw       = pb0;
            *(uint4*)(bsw + 8) = pb1;
            __syncthreads();
        }
    }

    // epilogue
#pragma unroll
    for (int im = 0; im < 4; im++) {
        const int r0 = bm + wm + im * 16 + gr;
#pragma unroll
        for (int in = 0; in < 4; in++) {
            const int col = bn + wn + in * 8 + 2 * tig;
            float2 v0 = make_float2(acc[im][in][0], acc[im][in][1]);
            float2 v1 = make_float2(acc[im][in][2], acc[im][in][3]);
            if (EPI == 2 || EPI == 3) {
                const float2 bb = *(const float2*)&bias[col];
                v0.x += bb.x; v0.y += bb.y;
                v1.x += bb.x; v1.y += bb.y;
            }
            if (EPI == 2) {
                v0.x = fmaxf(v0.x, 0.f); v0.y = fmaxf(v0.y, 0.f);
                v1.x = fmaxf(v1.x, 0.f); v1.y = fmaxf(v1.y, 0.f);
            }
            if (EPI == 1 || EPI == 3) {
                const float2 c0 = *(const float2*)&Cadd[(size_t)r0 * NC + col];
                const float2 c1 = *(const float2*)&Cadd[(size_t)(r0 + 8) * NC + col];
                v0.x += c0.x; v0.y += c0.y;
                v1.x += c1.x; v1.y += c1.y;
            }
            *(float2*)&C[(size_t)r0 * NC + col]       = v0;
            *(float2*)&C[(size_t)(r0 + 8) * NC + col] = v1;
        }
    }
}

__global__ __launch_bounds__(256) void k_proj_tc()
{ gemm_mma<Dd, DFF, 0>(g_h, g_Wh_qkv, nullptr, nullptr, g_proj); }

__global__ __launch_bounds__(256) void k_wo_tc()
{ gemm_mma<Dd, Dd, 1>(g_att, g_Wh_o, g_h, nullptr, g_hres); }

__global__ __launch_bounds__(256) void k_ffn1_tc(const float* __restrict__ b1)
{ gemm_mma<Dd, DFF, 2>(g_h2, g_Wh_1, nullptr, b1, g_ffn); }

__global__ __launch_bounds__(256) void k_ffn2_tc(const float* __restrict__ b2,
                                                 float* __restrict__ out)
{ gemm_mma<DFF, Dd, 3>(g_ffn, g_Wh_2, g_h2, b2, out); }

// ============================================================================
// Triangle attention v5 — 512 threads; warp-half h owns x in [x0h, x0h+4).
// rk/rv SMEM shared by both halves; double-buffered; f32x2; no-max softmax.
// ============================================================================
__global__ __launch_bounds__(512) void attn5_kernel()
{
    const int xt   = blockIdx.x;      // 0..7
    const int hh   = blockIdx.y;
    const int b    = blockIdx.z;
    const int t    = threadIdx.x;
    const int half = t >> 8;
    const int tl   = t & 255;
    const int y    = tl >> 2;
    const int dq   = tl & 3;
    const int x0   = xt * 8 + half * 4;

    __shared__ float rk_s[2][Nn][36];
    __shared__ float rv_s[2][Nn][36];
    __shared__ float lk_s[2][2][4][36];   // [half][buf][xr][col]
    __shared__ float lv_s[2][2][4][36];

    const int rr  = t >> 3;               // 0..63
    const int c4  = (t & 7) * 4;
    const int xr  = tl >> 3;               // 0..3 (tl<32)
    const int lc4 = (tl & 7) * 4;

    float4 prk, prv, plk, plv;
    uint32_t pmN, pmC;

    // ---- prefetch a = 0 ----
    {
        const int baseR = (b * Nn * Nn) * DFF + hh * DKk;
        prk = *(const float4*)&g_proj[baseR + rr * DFF + 256 + c4];
        prv = *(const float4*)&g_proj[baseR + rr * DFF + 768 + c4];
        if (tl < 32) {
            const int baseL = ((b * Nn + x0 + xr) * Nn) * DFF + hh * DKk;
            plk = *(const float4*)&g_proj[baseL + lc4];
            plv = *(const float4*)&g_proj[baseL + 512 + lc4];
        }
        pmN = *(const uint32_t*)&g_maskT[((b * Nn) * Nn + y) * 64 + x0];
    }
    *(float4*)&rk_s[0][rr][c4] = prk;
    *(float4*)&rv_s[0][rr][c4] = prv;
    if (tl < 32) {
        *(float4*)&lk_s[half][0][xr][lc4] = plk;
        *(float4*)&lv_s[half][0][xr][lc4] = plv;
    }
    __syncthreads();

    u64 acc[4][4];
    float l[4];
#pragma unroll
    for (int xx = 0; xx < 4; xx++) {
        l[xx] = 0.f;
#pragma unroll
        for (int j = 0; j < 4; j++) acc[xx][j] = 0ull;
    }

    for (int a = 0; a < Nn; a++) {
        const int buf = a & 1;

        pmC = pmN;
        if (a + 1 < Nn) {   // prefetch a+1 (overlaps compute)
            const int baseR = ((b * Nn + (a + 1)) * Nn) * DFF + hh * DKk;
            prk = *(const float4*)&g_proj[baseR + rr * DFF + 256 + c4];
            prv = *(const float4*)&g_proj[baseR + rr * DFF + 768 + c4];
            if (tl < 32) {
                const int baseL = ((b * Nn + x0 + xr) * Nn + (a + 1)) * DFF + hh * DKk;
                plk = *(const float4*)&g_proj[baseL + lc4];
                plv = *(const float4*)&g_proj[baseL + 512 + lc4];
            }
            pmN = *(const uint32_t*)&g_maskT[((b * Nn + (a + 1)) * Nn + y) * 64 + x0];
        }

        // ---- compute step a ----
        const ulonglong2 rka = *(const ulonglong2*)&rk_s[buf][y][dq * 8];
        const ulonglong2 rkb = *(const ulonglong2*)&rk_s[buf][y][dq * 8 + 4];
        const ulonglong2 rva = *(const ulonglong2*)&rv_s[buf][y][dq * 8];
        const ulonglong2 rvb = *(const ulonglong2*)&rv_s[buf][y][dq * 8 + 4];

#pragma unroll
        for (int xx = 0; xx < 4; xx++) {
            const ulonglong2 lka = *(const ulonglong2*)&lk_s[half][buf][xx][dq * 8];
            const ulonglong2 lkb = *(const ulonglong2*)&lk_s[half][buf][xx][dq * 8 + 4];
            u64 s2 = mul2(lka.x, rka.x);
            s2 = fma2(lka.y, rka.y, s2);
            s2 = fma2(lkb.x, rkb.x, s2);
            s2 = fma2(lkb.y, rkb.y, s2);
            float lo, hi;
            upk2(s2, lo, hi);
            float part = lo + hi;
            part += __shfl_xor_sync(0xffffffffu, part, 1);
            part += __shfl_xor_sync(0xffffffffu, part, 2);
            const float sc = ((pmC >> (xx * 8)) & 0xffu) ? -1e9f : part;
            const float p  = __expf(sc);
            l[xx] += p;
            const u64 pp = pk2(p, p);
            const ulonglong2 lva = *(const ulonglong2*)&lv_s[half][buf][xx][dq * 8];
            const ulonglong2 lvb = *(const ulonglong2*)&lv_s[half][buf][xx][dq * 8 + 4];
            acc[xx][0] = fma2(mul2(lva.x, rva.x), pp, acc[xx][0]);
            acc[xx][1] = fma2(mul2(lva.y, rva.y), pp, acc[xx][1]);
            acc[xx][2] = fma2(mul2(lvb.x, rvb.x), pp, acc[xx][2]);
            acc[xx][3] = fma2(mul2(lvb.y, rvb.y), pp, acc[xx][3]);
        }

        // ---- store prefetched a+1 ----
        if (a + 1 < Nn) {
            const int nb = buf ^ 1;
            *(float4*)&rk_s[nb][rr][c4] = prk;
            *(float4*)&rv_s[nb][rr][c4] = prv;
            if (tl < 32) {
                *(float4*)&lk_s[half][nb][xr][lc4] = plk;
                *(float4*)&lv_s[half][nb][xr][lc4] = plv;
            }
            __syncthreads();
        }
    }

#pragma unroll
    for (int xx = 0; xx < 4; xx++) {
        const float inv = 1.0f / l[xx];
        const int ob = ((b * Nn + x0 + xx) * Nn + y) * Dd + hh * DKk + dq * 8;
        float a0, a1, a2, a3, a4, a5, a6, a7;
        upk2(acc[xx][0], a0, a1);
        upk2(acc[xx][1], a2, a3);
        upk2(acc[xx][2], a4, a5);
        upk2(acc[xx][3], a6, a7);
        float4 v0, v1;
        v0.x = a0 * inv; v0.y = a1 * inv; v0.z = a2 * inv; v0.w = a3 * inv;
        v1.x = a4 * inv; v1.y = a5 * inv; v1.z = a6 * inv; v1.w = a7 * inv;
        *(float4*)&g_att[ob]     = v0;
        *(float4*)&g_att[ob + 4] = v1;
    }
}

// ============================================================================
// launch
// ============================================================================
extern "C" void kernel_launch(void* const* d_in, const int* in_sizes, int n_in,
                              void* d_out, int out_size)
{
    const float*         x    = (const float*)d_in[0];
    const unsigned char* mask = (const unsigned char*)d_in[1];
    const float*         Wlk  = (const float*)d_in[2];
    const float*         Wrk  = (const float*)d_in[3];
    const float*         Wlv  = (const float*)d_in[4];
    const float*         Wrv  = (const float*)d_in[5];
    const float*         Wo   = (const float*)d_in[6];
    const float*         W1   = (const float*)d_in[7];
    const float*         b1   = (const float*)d_in[8];
    const float*         W2   = (const float*)d_in[9];
    const float*         b2   = (const float*)d_in[10];
    const float*         g1   = (const float*)d_in[11];
    const float*         be1  = (const float*)d_in[12];
    const float*         g2   = (const float*)d_in[13];
    const float*         be2  = (const float*)d_in[14];
    float* out = (float*)d_out;

    k_prep<<<2880, 256>>>(Wlk, Wrk, Wlv, Wrv, Wo, W1, W2, mask);
    ln1_kernel<<<RR / 8, 256>>>(x, g1, be1);
    k_proj_tc<<<dim3(DFF / 128, RR / 128), 256>>>();
    attn5_kernel<<<dim3(8, Hh, Bb), 512>>>();
    k_wo_tc<<<dim3(Dd / 128, RR / 128), 256>>>();
    ln2_kernel<<<RR / 8, 256>>>(g2, be2);
    k_ffn1_tc<<<dim3(DFF / 128, RR / 128), 256>>>(b1);
    k_ffn2_tc<<<dim3(Dd / 128, RR / 128), 256>>>(b2, out);
}